// round 2
// baseline (speedup 1.0000x reference)
#include <cuda_runtime.h>
#include <cstdint>
#include <cstddef>

// Problem constants
#define T_STEPS 512
#define B_SZ    256
#define NI_SZ   128
#define K_SZ    512
#define NO_SZ   128

// Scratch (static device allocations; no cudaMalloc allowed)
// g_G   : per-phase pre-activation inputs G_c[m][r][b], reused across phases (max U=512 epochs)
// g_Hep : per-block epoch trajectories, 1020 epochs total of [64][256]
__device__ float g_G[512 * 64 * 256];
__device__ float g_Hep[1020 * 64 * 256];

__device__ __forceinline__ int hep_base(int j) { return 1024 - (1024 >> j); }

// 64x64 output tile micro-kernel: acc[4][4] per thread (to = row group, tb = col group)
__device__ __forceinline__ void mm_tile(const float (*As)[68], const float (*Bs)[68],
                                        int to, int tb, float acc[4][4])
{
#pragma unroll 16
    for (int kk = 0; kk < 64; kk++) {
        float4 bv = *(const float4*)&Bs[kk][tb * 4];
        float a0 = As[to * 4 + 0][kk];
        float a1 = As[to * 4 + 1][kk];
        float a2 = As[to * 4 + 2][kk];
        float a3 = As[to * 4 + 3][kk];
        acc[0][0] += a0 * bv.x; acc[0][1] += a0 * bv.y; acc[0][2] += a0 * bv.z; acc[0][3] += a0 * bv.w;
        acc[1][0] += a1 * bv.x; acc[1][1] += a1 * bv.y; acc[1][2] += a1 * bv.z; acc[1][3] += a1 * bv.w;
        acc[2][0] += a2 * bv.x; acc[2][1] += a2 * bv.y; acc[2][2] += a2 * bv.z; acc[2][3] += a2 * bv.w;
        acc[3][0] += a3 * bv.x; acc[3][1] += a3 * bv.y; acc[3][2] += a3 * bv.z; acc[3][3] += a3 * bv.w;
    }
}

// ---------------------------------------------------------------------------
// gather: G_c[m][r][b] = Wi[c-block] @ x_{t_m} + biases + sum_{j>c} Wh[c,j] @ H_j(epoch(t_m-1))
// grid (U_c, 4), 256 threads, output tile 64 rows x 64 batch
// ---------------------------------------------------------------------------
__global__ void __launch_bounds__(256) gather_kernel(const float* __restrict__ X,
                                                     const float* __restrict__ Wi,
                                                     const float* __restrict__ Wh,
                                                     int c)
{
    __shared__ float As[64][68];
    __shared__ float Bs[64][68];

    const int m   = blockIdx.x;
    const int b0  = blockIdx.y * 64;
    const int t   = m << c;
    const int tid = threadIdx.x;
    const int to  = tid >> 4;   // 0..15 -> rows to*4..to*4+3
    const int tb  = tid & 15;   // 0..15 -> cols tb*4..tb*4+3
    const int rowbase = c * 64;

    float acc[4][4];
#pragma unroll
    for (int q = 0; q < 4; q++)
#pragma unroll
        for (int u = 0; u < 4; u++) acc[q][u] = 0.f;

    // ---- Input projection chunks: k = h*64 .. h*64+63 over NI=128 ----
    for (int h = 0; h < 2; h++) {
        for (int idx = tid; idx < 4096; idx += 256) {
            int rr = idx >> 6, kk = idx & 63;
            As[rr][kk] = Wi[(size_t)(rowbase + rr) * 129 + h * 64 + kk];
        }
        for (int idx = tid; idx < 4096; idx += 256) {
            int bb = idx >> 6, kk = idx & 63;  // coalesced over kk
            Bs[kk][bb] = X[((size_t)t * B_SZ + b0 + bb) * NI_SZ + h * 64 + kk];
        }
        __syncthreads();
        mm_tile(As, Bs, to, tb, acc);
        __syncthreads();
    }

    // ---- Off-diagonal recurrent chunks from slower blocks (skip at t=0: H_prev = 0) ----
    if (m > 0) {
        for (int j = c + 1; j < 8; j++) {
            int e = (t - 1) >> j;
            const float* Hj = g_Hep + ((size_t)(hep_base(j) + e)) * 64 * 256;
            for (int idx = tid; idx < 4096; idx += 256) {
                int rr = idx >> 6, kk = idx & 63;
                As[rr][kk] = Wh[(size_t)(rowbase + rr) * 513 + j * 64 + kk];
            }
            for (int idx = tid; idx < 1024; idx += 256) {
                int kk = idx >> 4, b4 = idx & 15;
                *(float4*)&Bs[kk][b4 * 4] =
                    *(const float4*)&Hj[(size_t)kk * 256 + b0 + b4 * 4];
            }
            __syncthreads();
            mm_tile(As, Bs, to, tb, acc);
            __syncthreads();
        }
    }

    // ---- Epilogue: add both biases, write G ----
#pragma unroll
    for (int q = 0; q < 4; q++) {
        int r = to * 4 + q;
        float bias = Wi[(size_t)(rowbase + r) * 129 + 128]
                   + Wh[(size_t)(rowbase + r) * 513 + 512];
        float4 v = make_float4(acc[q][0] + bias, acc[q][1] + bias,
                               acc[q][2] + bias, acc[q][3] + bias);
        *(float4*)&g_G[((size_t)m * 64 + r) * 256 + b0 + tb * 4] = v;
    }
}

// ---------------------------------------------------------------------------
// seq: sequential diagonal recurrence for block c:
//   H_c[m] = tanh(G_c[m] + W_cc @ H_c[m-1]),  H_c[-1] = 0
// grid 128 CTAs (2 batch cols each), 128 threads: thread = (row r, local col lb)
// 64x64 diagonal weight row lives in registers; H exchanged via tiny SMEM buffer.
// ---------------------------------------------------------------------------
__global__ void __launch_bounds__(128) seq_kernel(const float* __restrict__ Wh, int c)
{
    const int U   = 512 >> c;
    const int tid = threadIdx.x;
    const int r   = tid >> 1;
    const int lb  = tid & 1;
    const int b   = blockIdx.x * 2 + lb;

    __shared__ float Hs[2][2][68];  // [buffer][lb][row]

    float w[64];
    const float* wr = Wh + (size_t)(c * 64 + r) * 513 + c * 64;
#pragma unroll
    for (int q = 0; q < 64; q++) w[q] = wr[q];

    float* Hb = g_Hep + (size_t)hep_base(c) * 64 * 256;

    float g = g_G[(size_t)r * 256 + b];  // G[0]
    int pbuf = 0;

    for (int m = 0; m < U; m++) {
        float acc = g;
        if (m > 0) {
            float a0 = 0.f, a1 = 0.f, a2 = 0.f, a3 = 0.f;
#pragma unroll
            for (int q = 0; q < 64; q += 4) {
                float4 hv = *(const float4*)&Hs[pbuf][lb][q];
                a0 += w[q + 0] * hv.x;
                a1 += w[q + 1] * hv.y;
                a2 += w[q + 2] * hv.z;
                a3 += w[q + 3] * hv.w;
            }
            acc += (a0 + a1) + (a2 + a3);
        }
        float h = tanhf(acc);
        Hb[((size_t)m * 64 + r) * 256 + b] = h;
        if (m + 1 < U) g = g_G[((size_t)(m + 1) * 64 + r) * 256 + b];  // prefetch next G
        Hs[pbuf ^ 1][lb][r] = h;
        __syncthreads();
        pbuf ^= 1;
    }
}

// ---------------------------------------------------------------------------
// out: Y[t][b][o] = tanh(Wo_b[o] + sum_j Wo[o, j-block] @ H_j(t>>j))
// grid (512, 4, 2), 256 threads, tile 64 o-rows x 64 batch
// ---------------------------------------------------------------------------
__global__ void __launch_bounds__(256) out_kernel(const float* __restrict__ Wo,
                                                  float* __restrict__ Y)
{
    __shared__ float As[64][68];
    __shared__ float Bs[64][68];

    const int t   = blockIdx.x;
    const int b0  = blockIdx.y * 64;
    const int o0  = blockIdx.z * 64;
    const int tid = threadIdx.x;
    const int to  = tid >> 4;
    const int tb  = tid & 15;

    float acc[4][4];
#pragma unroll
    for (int q = 0; q < 4; q++)
#pragma unroll
        for (int u = 0; u < 4; u++) acc[q][u] = 0.f;

    for (int j = 0; j < 8; j++) {
        int e = t >> j;
        const float* Hj = g_Hep + ((size_t)(hep_base(j) + e)) * 64 * 256;
        for (int idx = tid; idx < 4096; idx += 256) {
            int rr = idx >> 6, kk = idx & 63;
            As[rr][kk] = Wo[(size_t)(o0 + rr) * 513 + j * 64 + kk];
        }
        for (int idx = tid; idx < 1024; idx += 256) {
            int kk = idx >> 4, b4 = idx & 15;
            *(float4*)&Bs[kk][b4 * 4] =
                *(const float4*)&Hj[(size_t)kk * 256 + b0 + b4 * 4];
        }
        __syncthreads();
        mm_tile(As, Bs, to, tb, acc);
        __syncthreads();
    }

    // Epilogue: bias + tanh, store Y[t][b][o] (o contiguous)
    float yb[4];
#pragma unroll
    for (int q = 0; q < 4; q++)
        yb[q] = Wo[(size_t)(o0 + to * 4 + q) * 513 + 512];

#pragma unroll
    for (int u = 0; u < 4; u++) {
        float4 v = make_float4(tanhf(acc[0][u] + yb[0]),
                               tanhf(acc[1][u] + yb[1]),
                               tanhf(acc[2][u] + yb[2]),
                               tanhf(acc[3][u] + yb[3]));
        *(float4*)&Y[((size_t)t * B_SZ + b0 + tb * 4 + u) * NO_SZ + o0 + to * 4] = v;
    }
}

// ---------------------------------------------------------------------------
// final H: out[T*B*NO + k*256 + b] = last epoch of block k/64, row k%64
// ---------------------------------------------------------------------------
__global__ void __launch_bounds__(256) finalH_kernel(float* __restrict__ out)
{
    const int k = blockIdx.x;
    const int b = threadIdx.x;
    const int j = k >> 6, r = k & 63;
    const int e = (512 >> j) - 1;
    out[(size_t)T_STEPS * B_SZ * NO_SZ + (size_t)k * 256 + b] =
        g_Hep[((size_t)(hep_base(j) + e) * 64 + r) * 256 + b];
}

// ---------------------------------------------------------------------------
extern "C" void kernel_launch(void* const* d_in, const int* in_sizes, int n_in,
                              void* d_out, int out_size)
{
    // Defensive input identification by element count (metadata order: X, Wi, Wh, Wo)
    const float* X  = nullptr;
    const float* Wi = nullptr;
    const float* Wh = nullptr;
    const float* Wo = nullptr;
    for (int i = 0; i < n_in; i++) {
        switch (in_sizes[i]) {
            case 512 * 256 * 128: X  = (const float*)d_in[i]; break;  // 16777216
            case 512 * 129:       Wi = (const float*)d_in[i]; break;  // 66048
            case 512 * 513:       Wh = (const float*)d_in[i]; break;  // 262656
            case 128 * 513:       Wo = (const float*)d_in[i]; break;  // 65664
            default: break;
        }
    }
    float* out = (float*)d_out;

    // Hierarchical solve: slowest block first (block c depends only on blocks >= c)
    for (int c = 7; c >= 0; c--) {
        int U = 512 >> c;
        gather_kernel<<<dim3(U, 4), 256>>>(X, Wi, Wh, c);
        seq_kernel<<<128, 128>>>(Wh, c);
    }
    out_kernel<<<dim3(512, 4, 2), 256>>>(Wo, out);
    finalH_kernel<<<512, 256>>>(out);
}

// round 3
// speedup vs baseline: 1.4040x; 1.4040x over previous
#include <cuda_runtime.h>
#include <cstdint>
#include <cstddef>

#define T_STEPS 512
#define B_SZ    256
#define NI_SZ   128
#define K_SZ    512
#define NO_SZ   128

// ---------------------------------------------------------------------------
// Static scratch (no cudaMalloc allowed)
//  g_G   : per-phase pre-activations G_c[m][64][256] (reused per phase)
//  g_Hep : per-block epoch trajectories H_j[e][64][256], 1020 epochs total
//  g_P   : Wo-projections P_j[e][128][256], same epoch numbering as g_Hep
//  g_C   : off-diag projections C[c][j][e][64][256], 988 tiles total
// ---------------------------------------------------------------------------
__device__ float g_G  [512  * 64  * 256];
__device__ float g_Hep[1020 * 64  * 256];
__device__ float g_P  [1020 * 128 * 256];
__device__ float g_C  [988  * 64  * 256];

__device__ __forceinline__ int hep_base(int j) { return 1024 - (1024 >> j); }

// C tile index base per source block j (tiles of 64x256); consumer c adds c*U_j
__device__ __constant__ int c_S[8] = {0, 0, 256, 512, 704, 832, 912, 960};

// 64x64 output tile micro-kernel: acc[4][4] per thread
__device__ __forceinline__ void mm_tile(const float (*As)[68], const float (*Bs)[68],
                                        int to, int tb, float acc[4][4])
{
#pragma unroll 16
    for (int kk = 0; kk < 64; kk++) {
        float4 bv = *(const float4*)&Bs[kk][tb * 4];
        float a0 = As[to * 4 + 0][kk];
        float a1 = As[to * 4 + 1][kk];
        float a2 = As[to * 4 + 2][kk];
        float a3 = As[to * 4 + 3][kk];
        acc[0][0] += a0 * bv.x; acc[0][1] += a0 * bv.y; acc[0][2] += a0 * bv.z; acc[0][3] += a0 * bv.w;
        acc[1][0] += a1 * bv.x; acc[1][1] += a1 * bv.y; acc[1][2] += a1 * bv.z; acc[1][3] += a1 * bv.w;
        acc[2][0] += a2 * bv.x; acc[2][1] += a2 * bv.y; acc[2][2] += a2 * bv.z; acc[2][3] += a2 * bv.w;
        acc[3][0] += a3 * bv.x; acc[3][1] += a3 * bv.y; acc[3][2] += a3 * bv.z; acc[3][3] += a3 * bv.w;
    }
}

// ---------------------------------------------------------------------------
// gather: G_c[m] = Wi_c @ x_{m<<c} + biases + sum_{j>c} C[c][j][(m-1)>>(j-c)]
// grid (U_c, 4), 256 threads
// ---------------------------------------------------------------------------
__global__ void __launch_bounds__(256) gather_kernel(const float* __restrict__ X,
                                                     const float* __restrict__ Wi,
                                                     const float* __restrict__ Wh,
                                                     int c)
{
    __shared__ float As[64][68];
    __shared__ float Bs[64][68];

    const int m   = blockIdx.x;
    const int b0  = blockIdx.y * 64;
    const int t   = m << c;
    const int tid = threadIdx.x;
    const int to  = tid >> 4;
    const int tb  = tid & 15;
    const int rowbase = c * 64;

    float acc[4][4];
#pragma unroll
    for (int q = 0; q < 4; q++)
#pragma unroll
        for (int u = 0; u < 4; u++) acc[q][u] = 0.f;

    // Input projection: two K=64 chunks over NI=128
    for (int h = 0; h < 2; h++) {
        for (int idx = tid; idx < 4096; idx += 256) {
            int rr = idx >> 6, kk = idx & 63;
            As[rr][kk] = Wi[(size_t)(rowbase + rr) * 129 + h * 64 + kk];
        }
        for (int idx = tid; idx < 4096; idx += 256) {
            int bb = idx >> 6, kk = idx & 63;
            Bs[kk][bb] = X[((size_t)t * B_SZ + b0 + bb) * NI_SZ + h * 64 + kk];
        }
        __syncthreads();
        mm_tile(As, Bs, to, tb, acc);
        __syncthreads();
    }

    // Off-diagonal contributions: cached projection tiles
    if (m > 0) {
        for (int j = c + 1; j < 8; j++) {
            int e = (m - 1) >> (j - c);
            const float* Ct = g_C + ((size_t)(c_S[j] + c * (512 >> j) + e)) * (64 * 256);
#pragma unroll
            for (int q = 0; q < 4; q++) {
                float4 v = *(const float4*)&Ct[(size_t)(to * 4 + q) * 256 + b0 + tb * 4];
                acc[q][0] += v.x; acc[q][1] += v.y; acc[q][2] += v.z; acc[q][3] += v.w;
            }
        }
    }

    // Epilogue: biases, write G
#pragma unroll
    for (int q = 0; q < 4; q++) {
        int r = to * 4 + q;
        float bias = Wi[(size_t)(rowbase + r) * 129 + 128]
                   + Wh[(size_t)(rowbase + r) * 513 + 512];
        float4 v = make_float4(acc[q][0] + bias, acc[q][1] + bias,
                               acc[q][2] + bias, acc[q][3] + bias);
        *(float4*)&g_G[((size_t)m * 64 + r) * 256 + b0 + tb * 4] = v;
    }
}

// ---------------------------------------------------------------------------
// seq: H_c[m] = tanh(G_c[m] + W_cc @ H_c[m-1]),  H_c[-1] = 0
// grid 128 CTAs (2 batch cols each), 128 threads; diag weights in registers,
// H exchanged via SMEM; G prefetched 2 steps ahead.
// ---------------------------------------------------------------------------
__global__ void __launch_bounds__(128) seq_kernel(const float* __restrict__ Wh, int c)
{
    const int U   = 512 >> c;
    const int tid = threadIdx.x;
    const int r   = tid >> 1;
    const int lb  = tid & 1;
    const int b   = blockIdx.x * 2 + lb;

    __shared__ float Hs[2][2][68];

    float w[64];
    const float* wr = Wh + (size_t)(c * 64 + r) * 513 + c * 64;
#pragma unroll
    for (int q = 0; q < 64; q++) w[q] = wr[q];

    float* Hb = g_Hep + (size_t)hep_base(c) * 64 * 256;

    float g0 = g_G[(size_t)r * 256 + b];
    float g1 = (U > 1) ? g_G[(size_t)(64 * 256) + r * 256 + b] : 0.f;
    int pbuf = 0;

    for (int m = 0; m < U; m++) {
        float acc = g0;
        if (m > 0) {
            float a0 = 0.f, a1 = 0.f, a2 = 0.f, a3 = 0.f;
#pragma unroll
            for (int q = 0; q < 64; q += 4) {
                float4 hv = *(const float4*)&Hs[pbuf][lb][q];
                a0 += w[q + 0] * hv.x;
                a1 += w[q + 1] * hv.y;
                a2 += w[q + 2] * hv.z;
                a3 += w[q + 3] * hv.w;
            }
            acc += (a0 + a1) + (a2 + a3);
        }
        float h = tanhf(acc);
        Hb[((size_t)m * 64 + r) * 256 + b] = h;
        g0 = g1;
        if (m + 2 < U) g1 = g_G[((size_t)(m + 2) * 64 + r) * 256 + b];
        Hs[pbuf ^ 1][lb][r] = h;
        __syncthreads();
        pbuf ^= 1;
    }
}

// ---------------------------------------------------------------------------
// proj: for source block j, epoch e, compute the repeated-use projections:
//   z < j     : C[z][j][e] = Wh[z-rows, j-cols] @ H_j[e]   (64x256)
//   z >= j    : P_j[e] rows (z-j)*64..  = Wo[rows, j-cols] @ H_j[e]
// grid (U_j, 4, j+2), 256 threads, one K=64 chunk
// ---------------------------------------------------------------------------
__global__ void __launch_bounds__(256) proj_kernel(const float* __restrict__ Wh,
                                                   const float* __restrict__ Wo,
                                                   int j)
{
    __shared__ float As[64][68];
    __shared__ float Bs[64][68];

    const int e   = blockIdx.x;
    const int b0  = blockIdx.y * 64;
    const int z   = blockIdx.z;
    const int tid = threadIdx.x;
    const int to  = tid >> 4;
    const int tb  = tid & 15;

    // A: weight tile
    for (int idx = tid; idx < 4096; idx += 256) {
        int rr = idx >> 6, kk = idx & 63;
        As[rr][kk] = (z < j)
            ? Wh[(size_t)(z * 64 + rr) * 513 + j * 64 + kk]
            : Wo[(size_t)((z - j) * 64 + rr) * 513 + j * 64 + kk];
    }
    // B: H_j[e]
    const float* Hj = g_Hep + ((size_t)(hep_base(j) + e)) * 64 * 256;
    for (int idx = tid; idx < 1024; idx += 256) {
        int kk = idx >> 4, b4 = idx & 15;
        *(float4*)&Bs[kk][b4 * 4] = *(const float4*)&Hj[(size_t)kk * 256 + b0 + b4 * 4];
    }
    __syncthreads();

    float acc[4][4];
#pragma unroll
    for (int q = 0; q < 4; q++)
#pragma unroll
        for (int u = 0; u < 4; u++) acc[q][u] = 0.f;
    mm_tile(As, Bs, to, tb, acc);

    if (z < j) {
        float* Ct = g_C + ((size_t)(c_S[j] + z * (512 >> j) + e)) * (64 * 256);
#pragma unroll
        for (int q = 0; q < 4; q++)
            *(float4*)&Ct[(size_t)(to * 4 + q) * 256 + b0 + tb * 4] =
                make_float4(acc[q][0], acc[q][1], acc[q][2], acc[q][3]);
    } else {
        float* Pt = g_P + ((size_t)(hep_base(j) + e)) * (128 * 256)
                        + (size_t)(z - j) * 64 * 256;
#pragma unroll
        for (int q = 0; q < 4; q++)
            *(float4*)&Pt[(size_t)(to * 4 + q) * 256 + b0 + tb * 4] =
                make_float4(acc[q][0], acc[q][1], acc[q][2], acc[q][3]);
    }
}

// ---------------------------------------------------------------------------
// combine: Y[t][b][o] = tanh(Wo_bias[o] + sum_j P_j[t>>j][o][b])
// grid (512, 4), 256 threads; SMEM transpose for coalesced o-contiguous store.
// ---------------------------------------------------------------------------
__global__ void __launch_bounds__(256) combine_kernel(const float* __restrict__ Wo,
                                                      float* __restrict__ Y)
{
    __shared__ float S[128][68];

    const int t   = blockIdx.x;
    const int b0  = blockIdx.y * 64;
    const int tid = threadIdx.x;
    const int l16 = tid & 15;
    const int og  = tid >> 4;

    const float* pb[8];
#pragma unroll
    for (int j = 0; j < 8; j++)
        pb[j] = g_P + ((size_t)(hep_base(j) + (t >> j))) * (128 * 256) + b0 + l16 * 4;

#pragma unroll
    for (int i = 0; i < 8; i++) {
        int o = og + 16 * i;
        float bias = Wo[(size_t)o * 513 + 512];
        float4 a = make_float4(bias, bias, bias, bias);
#pragma unroll
        for (int j = 0; j < 8; j++) {
            float4 v = *(const float4*)&pb[j][(size_t)o * 256];
            a.x += v.x; a.y += v.y; a.z += v.z; a.w += v.w;
        }
        S[o][l16 * 4 + 0] = tanhf(a.x);
        S[o][l16 * 4 + 1] = tanhf(a.y);
        S[o][l16 * 4 + 2] = tanhf(a.z);
        S[o][l16 * 4 + 3] = tanhf(a.w);
    }
    __syncthreads();

    // coalesced store: Y[t][b][o], o contiguous
#pragma unroll
    for (int w = 0; w < 8; w++) {
        int idx = tid + w * 256;
        int bb  = idx >> 5;
        int o4  = (idx & 31) * 4;
        float4 v = make_float4(S[o4 + 0][bb], S[o4 + 1][bb], S[o4 + 2][bb], S[o4 + 3][bb]);
        *(float4*)&Y[((size_t)t * B_SZ + b0 + bb) * NO_SZ + o4] = v;
    }
}

// ---------------------------------------------------------------------------
// final H: out[T*B*NO + k*256 + b] = last epoch of block k/64, row k%64
// ---------------------------------------------------------------------------
__global__ void __launch_bounds__(256) finalH_kernel(float* __restrict__ out)
{
    const int k = blockIdx.x;
    const int b = threadIdx.x;
    const int j = k >> 6, r = k & 63;
    const int e = (512 >> j) - 1;
    out[(size_t)T_STEPS * B_SZ * NO_SZ + (size_t)k * 256 + b] =
        g_Hep[((size_t)(hep_base(j) + e) * 64 + r) * 256 + b];
}

// ---------------------------------------------------------------------------
extern "C" void kernel_launch(void* const* d_in, const int* in_sizes, int n_in,
                              void* d_out, int out_size)
{
    const float* X  = nullptr;
    const float* Wi = nullptr;
    const float* Wh = nullptr;
    const float* Wo = nullptr;
    for (int i = 0; i < n_in; i++) {
        switch (in_sizes[i]) {
            case 512 * 256 * 128: X  = (const float*)d_in[i]; break;
            case 512 * 129:       Wi = (const float*)d_in[i]; break;
            case 512 * 513:       Wh = (const float*)d_in[i]; break;
            case 128 * 513:       Wo = (const float*)d_in[i]; break;
            default: break;
        }
    }
    float* out = (float*)d_out;

    for (int c = 7; c >= 0; c--) {
        int U = 512 >> c;
        gather_kernel<<<dim3(U, 4), 256>>>(X, Wi, Wh, c);
        seq_kernel<<<128, 128>>>(Wh, c);
        proj_kernel<<<dim3(U, 4, c + 2), 256>>>(Wh, Wo, c);
    }
    combine_kernel<<<dim3(512, 4), 256>>>(Wo, out);
    finalH_kernel<<<512, 256>>>(out);
}

// round 4
// speedup vs baseline: 1.5724x; 1.1199x over previous
#include <cuda_runtime.h>
#include <cstdint>
#include <cstddef>

#define T_STEPS 512
#define B_SZ    256
#define NI_SZ   128
#define K_SZ    512
#define NO_SZ   128

// ---------------------------------------------------------------------------
// Static scratch.
// Layouts:
//   g_G   [tile][b(256)][r(64)]   tile = hep_base(c)+m   (seq-load friendly)
//   g_C   [ctile][b(256)][r(64)]
//   g_Hep [tile][b(256)][k(64)]   (proj B-matrix friendly: k contiguous)
//   g_P   [tile][b(256)][o(128)]  (combine friendly: o contiguous)
// ---------------------------------------------------------------------------
__device__ float g_G  [1020 * 64  * 256];
__device__ float g_Hep[1020 * 64  * 256];
__device__ float g_P  [1020 * 128 * 256];
__device__ float g_C  [988  * 64  * 256];

__device__ __constant__ int c_S[8] = {0, 0, 256, 512, 704, 832, 912, 960};

__device__ __forceinline__ int hep_base_d(int j) { return 1024 - (1024 >> j); }

__device__ __forceinline__ float ftanh(float x) {
    float t = __expf(2.0f * x);
    return 1.0f - __fdividef(2.0f, t + 1.0f);
}

// ---------------------------------------------------------------------------
// 64x64 GEMM µkernel: 128 threads, 4 rows x 8 cols per thread, K-chunks of 32.
// A source: row-major weights (lda 129/513). B source: [b][k] with k contiguous.
// ---------------------------------------------------------------------------
__device__ __forceinline__ void mm64(const float* __restrict__ Ag, int lda,
                                     const float* __restrict__ Bg, int ldb,
                                     int nchunks, float (&acc)[4][8],
                                     float (*As)[33], float (*Bs)[68], int tid)
{
    const int to = tid >> 3;  // 0..15 -> rows to*4..to*4+3
    const int tc = tid & 7;   // 0..7  -> cols tc*8..tc*8+7

    for (int ck = 0; ck < nchunks; ck++) {
        for (int idx = tid; idx < 2048; idx += 128) {
            int rr = idx >> 5, kk = idx & 31;
            As[rr][kk] = Ag[(size_t)rr * lda + ck * 32 + kk];
        }
        for (int idx = tid; idx < 2048; idx += 128) {
            int bb = idx >> 5, kk = idx & 31;
            Bs[kk][bb] = Bg[(size_t)bb * ldb + ck * 32 + kk];
        }
        __syncthreads();
#pragma unroll
        for (int kk = 0; kk < 32; kk++) {
            float4 bv0 = *(const float4*)&Bs[kk][tc * 8];
            float4 bv1 = *(const float4*)&Bs[kk][tc * 8 + 4];
            float b8[8] = {bv0.x, bv0.y, bv0.z, bv0.w, bv1.x, bv1.y, bv1.z, bv1.w};
            float a4[4] = {As[to * 4 + 0][kk], As[to * 4 + 1][kk],
                           As[to * 4 + 2][kk], As[to * 4 + 3][kk]};
#pragma unroll
            for (int q = 0; q < 4; q++)
#pragma unroll
                for (int u = 0; u < 8; u++) acc[q][u] += a4[q] * b8[u];
        }
        __syncthreads();
    }
}

// Transposed coalesced store: acc(row,col) -> out[(b0+col)*ldo + rowoff + row]
__device__ __forceinline__ void store_trans(float (&acc)[4][8], float (*S)[65],
                                            float* __restrict__ out, int ldo,
                                            int rowoff, int tid)
{
    const int to = tid >> 3, tc = tid & 7;
#pragma unroll
    for (int q = 0; q < 4; q++)
#pragma unroll
        for (int u = 0; u < 8; u++)
            S[tc * 8 + u][to * 4 + q] = acc[q][u];
    __syncthreads();
    for (int idx = tid; idx < 4096; idx += 128) {
        int rr = idx & 63, bb = idx >> 6;
        out[(size_t)bb * ldo + rowoff + rr] = S[bb][rr];
    }
}

#define DECL_SMEM() \
    __shared__ __align__(16) char smem_raw[17408]; \
    float (*As)[33] = reinterpret_cast<float(*)[33]>(smem_raw); \
    float (*Bs)[68] = reinterpret_cast<float(*)[68]>(smem_raw + 8448); \
    float (*S)[65]  = reinterpret_cast<float(*)[65]>(smem_raw)

// ---------------------------------------------------------------------------
// G0: all input projections + biases, for every (phase c, epoch m).
// grid (1020, 4), 128 threads. tile idx encodes (c, m) via hep_base.
// ---------------------------------------------------------------------------
__global__ void __launch_bounds__(128) g0_kernel(const float* __restrict__ X,
                                                 const float* __restrict__ Wi,
                                                 const float* __restrict__ Wh)
{
    DECL_SMEM();
    const int idx = blockIdx.x;
    const int v   = 1024 - idx;
    const int c   = __clz(v - 1) - 22;
    const int m   = idx - (1024 - (1024 >> c));
    const int t   = m << c;
    const int b0  = blockIdx.y * 64;
    const int tid = threadIdx.x;

    float acc[4][8];
#pragma unroll
    for (int q = 0; q < 4; q++)
#pragma unroll
        for (int u = 0; u < 8; u++) acc[q][u] = 0.f;

    mm64(Wi + (size_t)(c * 64) * 129, 129,
         X + ((size_t)t * 256 + b0) * 128, 128, 4, acc, As, Bs, tid);

    // add biases (Wi bias + Wh bias) per row
    const int to = tid >> 3;
#pragma unroll
    for (int q = 0; q < 4; q++) {
        int r = to * 4 + q;
        float bias = Wi[(size_t)(c * 64 + r) * 129 + 128]
                   + Wh[(size_t)(c * 64 + r) * 513 + 512];
#pragma unroll
        for (int u = 0; u < 8; u++) acc[q][u] += bias;
    }

    store_trans(acc, S, g_G + (size_t)idx * 16384 + (size_t)b0 * 64, 64, 0, tid);
}

// ---------------------------------------------------------------------------
// projC: C[z][j][e] = Wh[z-rows, j-cols] @ H_j[e],  z < j (consumers).
// grid (U_j, 4, j), 128 threads.
// ---------------------------------------------------------------------------
__global__ void __launch_bounds__(128) projC_kernel(const float* __restrict__ Wh, int j)
{
    DECL_SMEM();
    const int e   = blockIdx.x;
    const int b0  = blockIdx.y * 64;
    const int z   = blockIdx.z;
    const int tid = threadIdx.x;

    float acc[4][8];
#pragma unroll
    for (int q = 0; q < 4; q++)
#pragma unroll
        for (int u = 0; u < 8; u++) acc[q][u] = 0.f;

    mm64(Wh + (size_t)(z * 64) * 513 + j * 64, 513,
         g_Hep + (size_t)(hep_base_d(j) + e) * 16384 + (size_t)b0 * 64, 64,
         2, acc, As, Bs, tid);

    int ctile = c_S[j] + z * gridDim.x + e;
    store_trans(acc, S, g_C + (size_t)ctile * 16384 + (size_t)b0 * 64, 64, 0, tid);
}

// ---------------------------------------------------------------------------
// projP: P_j[e] rows z*64.. = Wo[rows, j-cols] @ H_j[e]. Batched over all (j,e).
// grid (1020, 4, 2), 128 threads.
// ---------------------------------------------------------------------------
__global__ void __launch_bounds__(128) projP_kernel(const float* __restrict__ Wo)
{
    DECL_SMEM();
    const int idx = blockIdx.x;
    const int v   = 1024 - idx;
    const int j   = __clz(v - 1) - 22;
    const int e   = idx - (1024 - (1024 >> j));
    const int b0  = blockIdx.y * 64;
    const int z   = blockIdx.z;
    const int tid = threadIdx.x;

    float acc[4][8];
#pragma unroll
    for (int q = 0; q < 4; q++)
#pragma unroll
        for (int u = 0; u < 8; u++) acc[q][u] = 0.f;

    mm64(Wo + (size_t)(z * 64) * 513 + j * 64, 513,
         g_Hep + (size_t)(hep_base_d(j) + e) * 16384 + (size_t)b0 * 64, 64,
         2, acc, As, Bs, tid);

    store_trans(acc, S, g_P + (size_t)idx * 32768 + (size_t)b0 * 128, 128, z * 64, tid);
}

// ---------------------------------------------------------------------------
// seq<C>: H_c[m] = tanh(G0[m] + sum_{j>c} C[c][j][(m-1)>>(j-c)] + W_cc @ H[m-1])
// 128 CTAs x 2 batch cols, 256 threads: k-split dot (hh halves), depth-4 prefetch.
// ---------------------------------------------------------------------------
template <int NS>
__device__ __forceinline__ void fetchv(float (&dst)[NS], int m, int U,
                                       const float* __restrict__ Gb,
                                       const float* const (&Cb)[NS],
                                       int off, int hh)
{
    if (hh || m >= U) return;
    dst[0] = Gb[(size_t)m * 16384 + off];
    if (m > 0) {
#pragma unroll
        for (int s = 1; s < NS; s++)
            dst[s] = Cb[s][(size_t)((m - 1) >> s) * 16384 + off];
    }
}

template <int C>
__global__ void __launch_bounds__(256) seq_kernel(const float* __restrict__ Wh)
{
    constexpr int U  = 512 >> C;
    constexpr int NS = (C == 7) ? 1 : (8 - C);
    constexpr int HB = 1024 - (1024 >> C);
    constexpr int cs[8] = {0, 0, 256, 512, 704, 832, 912, 960};

    const int tid = threadIdx.x;
    const int hh  = tid >> 7;          // k-half
    const int r   = tid & 63;
    const int lb  = (tid >> 6) & 1;
    const int b   = blockIdx.x * 2 + lb;
    const int off = b * 64 + r;

    __shared__ float Ws[64][65];
    __shared__ float Hs[2][2][68];
    __shared__ float Ps[2][68];

    for (int idx = tid; idx < 4096; idx += 256) {
        int rr = idx >> 6, kk = idx & 63;
        Ws[rr][kk] = Wh[(size_t)(C * 64 + rr) * 513 + C * 64 + kk];
    }
    __syncthreads();

    float w[32];
#pragma unroll
    for (int q = 0; q < 32; q++) w[q] = Ws[r][hh * 32 + q];

    const float* Gb = g_G + (size_t)HB * 16384;
    float*       Hb = g_Hep + (size_t)HB * 16384;
    const float* Cb[NS];
    Cb[0] = nullptr;
#pragma unroll
    for (int s = 1; s < NS; s++)
        Cb[s] = g_C + (size_t)(cs[C + s] + C * (512 >> (C + s))) * 16384;

    auto step = [&](int m, const float (&vv)[NS]) {
        float p = 0.f;
        const int rb = m & 1;
        if (m > 0) {
            float a0 = 0.f, a1 = 0.f, a2 = 0.f, a3 = 0.f;
#pragma unroll
            for (int q = 0; q < 32; q += 4) {
                float4 hv = *(const float4*)&Hs[rb][lb][hh * 32 + q];
                a0 += w[q + 0] * hv.x;
                a1 += w[q + 1] * hv.y;
                a2 += w[q + 2] * hv.z;
                a3 += w[q + 3] * hv.w;
            }
            p = (a0 + a1) + (a2 + a3);
        }
        if (hh) Ps[lb][r] = p;
        __syncthreads();
        if (!hh) {
            float a = vv[0];
            if (m > 0) {
                a += p + Ps[lb][r];
#pragma unroll
                for (int s = 1; s < NS; s++) a += vv[s];
            }
            float h = ftanh(a);
            Hb[(size_t)m * 16384 + off] = h;
            Hs[rb ^ 1][lb][r] = h;
        }
        __syncthreads();
    };

    float v0[NS], v1[NS], v2[NS], v3[NS];
    fetchv<NS>(v0, 0, U, Gb, Cb, off, hh);
    fetchv<NS>(v1, 1, U, Gb, Cb, off, hh);
    fetchv<NS>(v2, 2, U, Gb, Cb, off, hh);
    fetchv<NS>(v3, 3, U, Gb, Cb, off, hh);

    for (int m = 0; m < U; m += 4) {
        step(m + 0, v0); fetchv<NS>(v0, m + 4, U, Gb, Cb, off, hh);
        step(m + 1, v1); fetchv<NS>(v1, m + 5, U, Gb, Cb, off, hh);
        step(m + 2, v2); fetchv<NS>(v2, m + 6, U, Gb, Cb, off, hh);
        step(m + 3, v3); fetchv<NS>(v3, m + 7, U, Gb, Cb, off, hh);
    }
}

// ---------------------------------------------------------------------------
// combine: Y[t][b][o] = tanh(Wo_bias[o] + sum_j P_j[t>>j][b][o])
// grid (512, 4), 256 threads. Fully coalesced (o contiguous everywhere).
// ---------------------------------------------------------------------------
__global__ void __launch_bounds__(256) combine_kernel(const float* __restrict__ Wo,
                                                      float* __restrict__ Y)
{
    const int t   = blockIdx.x;
    const int b0  = blockIdx.y * 64;
    const int tid = threadIdx.x;
    const int o4  = (tid & 31) * 4;
    const int bb0 = tid >> 5;

    const float* pb[8];
#pragma unroll
    for (int j = 0; j < 8; j++)
        pb[j] = g_P + (size_t)(hep_base_d(j) + (t >> j)) * 32768 + o4;

    float4 bias = make_float4(Wo[(size_t)(o4 + 0) * 513 + 512],
                              Wo[(size_t)(o4 + 1) * 513 + 512],
                              Wo[(size_t)(o4 + 2) * 513 + 512],
                              Wo[(size_t)(o4 + 3) * 513 + 512]);

#pragma unroll
    for (int i = 0; i < 8; i++) {
        int bb = b0 + bb0 + i * 8;
        float4 a = bias;
#pragma unroll
        for (int j = 0; j < 8; j++) {
            float4 p = *(const float4*)&pb[j][(size_t)bb * 128];
            a.x += p.x; a.y += p.y; a.z += p.z; a.w += p.w;
        }
        float4 y = make_float4(ftanh(a.x), ftanh(a.y), ftanh(a.z), ftanh(a.w));
        *(float4*)&Y[((size_t)t * 256 + bb) * 128 + o4] = y;
    }
}

// ---------------------------------------------------------------------------
// final H: out[T*B*NO + (j*64+r)*256 + b] = H_j[last epoch][b][r] (transpose)
// grid (8, 4), 256 threads.
// ---------------------------------------------------------------------------
__global__ void __launch_bounds__(256) finalH_kernel(float* __restrict__ out)
{
    __shared__ float S[64][65];
    const int j   = blockIdx.x;
    const int b0  = blockIdx.y * 64;
    const int tid = threadIdx.x;
    const int e   = (512 >> j) - 1;
    const float* Hj = g_Hep + (size_t)(hep_base_d(j) + e) * 16384;

    for (int idx = tid; idx < 4096; idx += 256) {
        int rr = idx & 63, bb = idx >> 6;
        S[bb][rr] = Hj[(size_t)(b0 + bb) * 64 + rr];
    }
    __syncthreads();
    for (int idx = tid; idx < 4096; idx += 256) {
        int bb = idx & 63, rr = idx >> 6;
        out[(size_t)T_STEPS * B_SZ * NO_SZ + (size_t)(j * 64 + rr) * 256 + b0 + bb] =
            S[bb][rr];
    }
}

// ---------------------------------------------------------------------------
extern "C" void kernel_launch(void* const* d_in, const int* in_sizes, int n_in,
                              void* d_out, int out_size)
{
    const float* X  = nullptr;
    const float* Wi = nullptr;
    const float* Wh = nullptr;
    const float* Wo = nullptr;
    for (int i = 0; i < n_in; i++) {
        switch (in_sizes[i]) {
            case 512 * 256 * 128: X  = (const float*)d_in[i]; break;
            case 512 * 129:       Wi = (const float*)d_in[i]; break;
            case 512 * 513:       Wh = (const float*)d_in[i]; break;
            case 128 * 513:       Wo = (const float*)d_in[i]; break;
            default: break;
        }
    }
    float* out = (float*)d_out;

    g0_kernel<<<dim3(1020, 4), 128>>>(X, Wi, Wh);

    seq_kernel<7><<<128, 256>>>(Wh);
    projC_kernel<<<dim3(4, 4, 7), 128>>>(Wh, 7);
    seq_kernel<6><<<128, 256>>>(Wh);
    projC_kernel<<<dim3(8, 4, 6), 128>>>(Wh, 6);
    seq_kernel<5><<<128, 256>>>(Wh);
    projC_kernel<<<dim3(16, 4, 5), 128>>>(Wh, 5);
    seq_kernel<4><<<128, 256>>>(Wh);
    projC_kernel<<<dim3(32, 4, 4), 128>>>(Wh, 4);
    seq_kernel<3><<<128, 256>>>(Wh);
    projC_kernel<<<dim3(64, 4, 3), 128>>>(Wh, 3);
    seq_kernel<2><<<128, 256>>>(Wh);
    projC_kernel<<<dim3(128, 4, 2), 128>>>(Wh, 2);
    seq_kernel<1><<<128, 256>>>(Wh);
    projC_kernel<<<dim3(256, 4, 1), 128>>>(Wh, 1);
    seq_kernel<0><<<128, 256>>>(Wh);

    projP_kernel<<<dim3(1020, 4, 2), 128>>>(Wo);
    combine_kernel<<<dim3(512, 4), 256>>>(Wo, out);
    finalH_kernel<<<dim3(8, 4), 256>>>(out);
}

// round 6
// speedup vs baseline: 2.5630x; 1.6300x over previous
#include <cuda_runtime.h>
#include <cuda_bf16.h>
#include <cstdint>
#include <cstddef>

#define T_STEPS 512
#define B_SZ    256
#define NO_SZ   128

// ---------------------------------------------------------------------------
// Static scratch.
//   g_G   [tile][b(256)][r(64)]    tile = hep_base(c)+m   (input+bias preacts)
//   g_Hep [tile][b(256)][k(64)]    hidden epochs
//   g_R   [tile][b(256)][o(128)]   prefix-summed output projections
//   g_C   [ctile][b(256)][r(64)]   off-diagonal recurrent projections
// ---------------------------------------------------------------------------
__device__ float g_G  [1020u * 64  * 256];
__device__ float g_Hep[1020u * 64  * 256];
__device__ float g_R  [1020u * 128 * 256];
__device__ float g_C  [988u  * 64  * 256];

__device__ __constant__ int c_S[8] = {0, 0, 256, 512, 704, 832, 912, 960};

__device__ __forceinline__ int hb(int j) { return 1024 - (1024 >> j); }

__device__ __forceinline__ float ftanh(float x) {
    float t = __expf(2.0f * x);
    return 1.0f - __fdividef(2.0f, t + 1.0f);
}

// ---------------------------------------------------------------------------
// bf16 MMA m16n8k16 (row.col, f32 accum)
// ---------------------------------------------------------------------------
__device__ __forceinline__ void mma_bf16(float* d, const uint32_t* a, const uint32_t* b)
{
    asm volatile(
        "mma.sync.aligned.m16n8k16.row.col.f32.bf16.bf16.f32 "
        "{%0,%1,%2,%3},{%4,%5,%6,%7},{%8,%9},{%0,%1,%2,%3};\n"
        : "+f"(d[0]), "+f"(d[1]), "+f"(d[2]), "+f"(d[3])
        : "r"(a[0]), "r"(a[1]), "r"(a[2]), "r"(a[3]), "r"(b[0]), "r"(b[1]));
}

__device__ __forceinline__ uint32_t pack2(float x0, float x1, bool lo)
{
    __nv_bfloat16 h0 = __float2bfloat16(x0);
    __nv_bfloat16 h1 = __float2bfloat16(x1);
    if (lo) {
        h0 = __float2bfloat16(x0 - __bfloat162float(h0));
        h1 = __float2bfloat16(x1 - __bfloat162float(h1));
    }
    __nv_bfloat162 p = __halves2bfloat162(h0, h1);
    return *reinterpret_cast<uint32_t*>(&p);
}

// Shared layout (uint32 words), total 9216 words = 36864 B:
//   AH [64][36] @0   AL [64][36] @2304   BH [64][36] @4608   BL [64][36] @6912
//   S  (float [64][68]) overlays BH/BL region (@4608, 4352 floats <= 4608)
#define AH_OFF 0
#define AL_OFF 2304
#define BH_OFF 4608
#define BL_OFF 6912

// Stage A (64 rows x 64 k, row-major lda) and B (64 cols x 64 k, k-contig ldb).
// koff applies to BOTH A and B k-indices; pass base (unoffset) pointers.
__device__ __forceinline__ void stage_AB(uint32_t* su,
                                         const float* __restrict__ Ag, int lda, int koff,
                                         const float* __restrict__ Bg, int ldb,
                                         int tid)
{
    for (int idx = tid; idx < 64 * 32; idx += 256) {
        int r = idx >> 5, p = idx & 31;
        float x0 = Ag[(size_t)r * lda + koff + 2 * p];
        float x1 = Ag[(size_t)r * lda + koff + 2 * p + 1];
        su[AH_OFF + r * 36 + p] = pack2(x0, x1, false);
        su[AL_OFF + r * 36 + p] = pack2(x0, x1, true);
    }
    for (int idx = tid; idx < 64 * 16; idx += 256) {
        int c = idx >> 4, q = idx & 15;
        float4 v = *(const float4*)&Bg[(size_t)c * ldb + koff + 4 * q];
        su[BH_OFF + c * 36 + 2 * q]     = pack2(v.x, v.y, false);
        su[BL_OFF + c * 36 + 2 * q]     = pack2(v.x, v.y, true);
        su[BH_OFF + c * 36 + 2 * q + 1] = pack2(v.z, v.w, false);
        su[BL_OFF + c * 36 + 2 * q + 1] = pack2(v.z, v.w, true);
    }
}

// 64x64 tile MMA: warp w -> rows (w&3)*16.., cols (w>>2)*32..; acc[4][4]
__device__ __forceinline__ void mma_block(const uint32_t* su, int warp, int lane,
                                          float (&acc)[4][4])
{
    const int mrow = (warp & 3) * 16;
    const int nb   = (warp >> 2) * 32;
    const int gr   = lane >> 2, tg = lane & 3;
#pragma unroll
    for (int c = 0; c < 4; c++) {
        const int pb = c * 8;
        uint32_t ah[4], al[4];
        ah[0] = su[AH_OFF + (mrow + gr)     * 36 + pb + tg];
        ah[1] = su[AH_OFF + (mrow + gr + 8) * 36 + pb + tg];
        ah[2] = su[AH_OFF + (mrow + gr)     * 36 + pb + 4 + tg];
        ah[3] = su[AH_OFF + (mrow + gr + 8) * 36 + pb + 4 + tg];
        al[0] = su[AL_OFF + (mrow + gr)     * 36 + pb + tg];
        al[1] = su[AL_OFF + (mrow + gr + 8) * 36 + pb + tg];
        al[2] = su[AL_OFF + (mrow + gr)     * 36 + pb + 4 + tg];
        al[3] = su[AL_OFF + (mrow + gr + 8) * 36 + pb + 4 + tg];
#pragma unroll
        for (int nt = 0; nt < 4; nt++) {
            const int colb = nb + nt * 8 + gr;
            uint32_t bh[2], bl[2];
            bh[0] = su[BH_OFF + colb * 36 + pb + tg];
            bh[1] = su[BH_OFF + colb * 36 + pb + 4 + tg];
            bl[0] = su[BL_OFF + colb * 36 + pb + tg];
            bl[1] = su[BL_OFF + colb * 36 + pb + 4 + tg];
            mma_bf16(acc[nt], ah, bh);
            mma_bf16(acc[nt], ah, bl);
            mma_bf16(acc[nt], al, bh);
        }
    }
}

// acc -> S[col][row] transpose staging (S overlays B smem region)
__device__ __forceinline__ void acc_to_S(float* Sf, int warp, int lane, float (&acc)[4][4])
{
    const int mrow = (warp & 3) * 16;
    const int nb   = (warp >> 2) * 32;
    const int gr   = lane >> 2, tg = lane & 3;
#pragma unroll
    for (int nt = 0; nt < 4; nt++) {
        const int c0 = nb + nt * 8 + 2 * tg;
        Sf[(size_t)c0       * 68 + mrow + gr]     = acc[nt][0];
        Sf[(size_t)(c0 + 1) * 68 + mrow + gr]     = acc[nt][1];
        Sf[(size_t)c0       * 68 + mrow + gr + 8] = acc[nt][2];
        Sf[(size_t)(c0 + 1) * 68 + mrow + gr + 8] = acc[nt][3];
    }
}

// ---------------------------------------------------------------------------
// g0: G[c][m] = Wi_c @ x_{m<<c} + (Wi_bias + Wh_bias).  grid (1020, 4), 256 thr.
// ---------------------------------------------------------------------------
__global__ void __launch_bounds__(256) g0_kernel(const float* __restrict__ X,
                                                 const float* __restrict__ Wi,
                                                 const float* __restrict__ Wh)
{
    __shared__ __align__(16) uint32_t su[9216];
    float* Sf = (float*)(su + BH_OFF);

    const int idx = blockIdx.x;
    const int v   = 1024 - idx;
    const int c   = __clz(v - 1) - 22;
    const int m   = idx - (1024 - (1024 >> c));
    const int t   = m << c;
    const int b0  = blockIdx.y * 64;
    const int tid = threadIdx.x;
    const int warp = tid >> 5, lane = tid & 31;

    const float* Ag = Wi + (size_t)(c * 64) * 129;
    const float* Bg = X + ((size_t)t * 256 + b0) * 128;

    float acc[4][4];
#pragma unroll
    for (int q = 0; q < 4; q++)
#pragma unroll
        for (int u = 0; u < 4; u++) acc[q][u] = 0.f;

    for (int kh = 0; kh < 2; kh++) {
        // koff applies to both A and B inside stage_AB (bugfix: no double offset)
        stage_AB(su, Ag, 129, kh * 64, Bg, 128, tid);
        __syncthreads();
        mma_block(su, warp, lane, acc);
        __syncthreads();
    }

    // biases per output row
    {
        const int mrow = (warp & 3) * 16, gr = lane >> 2;
        int r0 = c * 64 + mrow + gr, r1 = r0 + 8;
        float ba = Wi[(size_t)r0 * 129 + 128] + Wh[(size_t)r0 * 513 + 512];
        float bb = Wi[(size_t)r1 * 129 + 128] + Wh[(size_t)r1 * 513 + 512];
#pragma unroll
        for (int nt = 0; nt < 4; nt++) {
            acc[nt][0] += ba; acc[nt][1] += ba;
            acc[nt][2] += bb; acc[nt][3] += bb;
        }
    }

    acc_to_S(Sf, warp, lane, acc);
    __syncthreads();

    float* out = g_G + (size_t)idx * 16384 + (size_t)b0 * 64;
    for (int i = tid; i < 64 * 16; i += 256) {
        int col = i >> 4, rq = i & 15;
        *(float4*)&out[(size_t)col * 64 + rq * 4] = *(float4*)&Sf[(size_t)col * 68 + rq * 4];
    }
}

// ---------------------------------------------------------------------------
// proj: for source block j, epoch e, batch-group b0, role z:
//   z < j  : g_C tile (Wh consumer z)
//   z >= j : R_j rows (z-j)*64.. = Wo-proj + parent R_{j+1}[e>>1] (+bias at j=7)
//            j == 0: tanh -> Y directly.
// grid (U_j, 4, j+2), 256 threads.
// ---------------------------------------------------------------------------
__global__ void __launch_bounds__(256) proj_kernel(const float* __restrict__ Wh,
                                                   const float* __restrict__ Wo,
                                                   float* __restrict__ Y, int j)
{
    __shared__ __align__(16) uint32_t su[9216];
    float* Sf = (float*)(su + BH_OFF);

    const int e   = blockIdx.x;
    const int U   = gridDim.x;
    const int b0  = blockIdx.y * 64;
    const int z   = blockIdx.z;
    const int tid = threadIdx.x;
    const int warp = tid >> 5, lane = tid & 31;

    const float* Ag = (z < j) ? Wh + (size_t)(z * 64) * 513 + j * 64
                              : Wo + (size_t)((z - j) * 64) * 513 + j * 64;
    const float* Bg = g_Hep + (size_t)(hb(j) + e) * 16384 + (size_t)b0 * 64;

    float acc[4][4];
#pragma unroll
    for (int q = 0; q < 4; q++)
#pragma unroll
        for (int u = 0; u < 4; u++) acc[q][u] = 0.f;

    stage_AB(su, Ag, 513, 0, Bg, 64, tid);
    __syncthreads();
    mma_block(su, warp, lane, acc);
    __syncthreads();
    acc_to_S(Sf, warp, lane, acc);
    __syncthreads();

    if (z < j) {
        float* out = g_C + (size_t)(c_S[j] + z * U + e) * 16384 + (size_t)b0 * 64;
        for (int i = tid; i < 64 * 16; i += 256) {
            int col = i >> 4, rq = i & 15;
            *(float4*)&out[(size_t)col * 64 + rq * 4] =
                *(float4*)&Sf[(size_t)col * 68 + rq * 4];
        }
    } else {
        const int o0 = (z - j) * 64;
        const float* Rpar = (j < 7)
            ? g_R + (size_t)(hb(j + 1) + (e >> 1)) * 32768
            : nullptr;
        for (int i = tid; i < 64 * 16; i += 256) {
            int col = i >> 4, rq = i & 15;
            float4 s = *(float4*)&Sf[(size_t)col * 68 + rq * 4];
            if (j < 7) {
                float4 p = *(const float4*)&Rpar[(size_t)(b0 + col) * 128 + o0 + rq * 4];
                s.x += p.x; s.y += p.y; s.z += p.z; s.w += p.w;
            } else {
                s.x += Wo[(size_t)(o0 + rq * 4 + 0) * 513 + 512];
                s.y += Wo[(size_t)(o0 + rq * 4 + 1) * 513 + 512];
                s.z += Wo[(size_t)(o0 + rq * 4 + 2) * 513 + 512];
                s.w += Wo[(size_t)(o0 + rq * 4 + 3) * 513 + 512];
            }
            if (j == 0) {
                float4 y = make_float4(ftanh(s.x), ftanh(s.y), ftanh(s.z), ftanh(s.w));
                *(float4*)&Y[((size_t)e * 256 + b0 + col) * 128 + o0 + rq * 4] = y;
            } else {
                *(float4*)&g_R[(size_t)(hb(j) + e) * 32768 +
                               (size_t)(b0 + col) * 128 + o0 + rq * 4] = s;
            }
        }
    }
}

// ---------------------------------------------------------------------------
// seq<C>: H[m] = tanh(G[m] + sum_{j>C} C[C][j][(m-1)>>(j-C)] + W_CC @ H[m-1])
// grid 128 CTAs x 2 batch cols, 128 threads (thread = (col, full 64-dot row)).
// ---------------------------------------------------------------------------
template <int NS>
__device__ __forceinline__ void fetchv(float (&dst)[NS], int m, int U,
                                       const float* __restrict__ Gb,
                                       const float* const (&Cb)[NS], int off)
{
    if (m >= U) return;
    dst[0] = Gb[(size_t)m * 16384 + off];
    if (m > 0) {
#pragma unroll
        for (int s = 1; s < NS; s++)
            dst[s] = Cb[s][(size_t)((m - 1) >> s) * 16384 + off];
    }
}

template <int C>
__global__ void __launch_bounds__(128) seq_kernel(const float* __restrict__ Wh)
{
    constexpr int U  = 512 >> C;
    constexpr int NS = (C == 7) ? 1 : (8 - C);
    constexpr int HB = 1024 - (1024 >> C);
    constexpr int csl[8] = {0, 0, 256, 512, 704, 832, 912, 960};

    const int tid = threadIdx.x;
    const int lb  = tid >> 6;
    const int r   = tid & 63;
    const int b   = blockIdx.x * 2 + lb;
    const int off = b * 64 + r;

    __shared__ float Ws[64][65];
    __shared__ float Hs[2][2][64];

    for (int i = tid; i < 4096; i += 128)
        Ws[i >> 6][i & 63] = Wh[(size_t)(C * 64 + (i >> 6)) * 513 + C * 64 + (i & 63)];
    __syncthreads();

    float w[64];
#pragma unroll
    for (int q = 0; q < 64; q++) w[q] = Ws[r][q];

    const float* Gb = g_G + (size_t)HB * 16384;
    float*       Hbp = g_Hep + (size_t)HB * 16384;
    const float* Cb[NS];
    Cb[0] = nullptr;
#pragma unroll
    for (int s = 1; s < NS; s++)
        Cb[s] = g_C + (size_t)(csl[C + s] + C * (512 >> (C + s))) * 16384;

    auto step = [&](int m, const float (&vv)[NS]) {
        const int rb = m & 1;
        float a = vv[0];
        if (m > 0) {
            float a0 = 0.f, a1 = 0.f, a2 = 0.f, a3 = 0.f;
#pragma unroll
            for (int q = 0; q < 64; q += 4) {
                float4 hv = *(const float4*)&Hs[rb][lb][q];
                a0 += w[q + 0] * hv.x;
                a1 += w[q + 1] * hv.y;
                a2 += w[q + 2] * hv.z;
                a3 += w[q + 3] * hv.w;
            }
            a += (a0 + a1) + (a2 + a3);
#pragma unroll
            for (int s = 1; s < NS; s++) a += vv[s];
        }
        float h = ftanh(a);
        Hbp[(size_t)m * 16384 + off] = h;
        Hs[rb ^ 1][lb][r] = h;
        __syncthreads();
    };

    float v0[NS], v1[NS], v2[NS], v3[NS];
    fetchv<NS>(v0, 0, U, Gb, Cb, off);
    fetchv<NS>(v1, 1, U, Gb, Cb, off);
    fetchv<NS>(v2, 2, U, Gb, Cb, off);
    fetchv<NS>(v3, 3, U, Gb, Cb, off);

    for (int m = 0; m < U; m += 4) {
        step(m + 0, v0); fetchv<NS>(v0, m + 4, U, Gb, Cb, off);
        step(m + 1, v1); fetchv<NS>(v1, m + 5, U, Gb, Cb, off);
        step(m + 2, v2); fetchv<NS>(v2, m + 6, U, Gb, Cb, off);
        step(m + 3, v3); fetchv<NS>(v3, m + 7, U, Gb, Cb, off);
    }
}

// ---------------------------------------------------------------------------
// final H: out[T*B*NO + (j*64+r)*256 + b] = H_j[last epoch][b][r] (transpose)
// ---------------------------------------------------------------------------
__global__ void __launch_bounds__(256) finalH_kernel(float* __restrict__ out)
{
    __shared__ float S[64][65];
    const int j   = blockIdx.x;
    const int b0  = blockIdx.y * 64;
    const int tid = threadIdx.x;
    const int e   = (512 >> j) - 1;
    const float* Hj = g_Hep + (size_t)(hb(j) + e) * 16384;

    for (int i = tid; i < 4096; i += 256) {
        int rr = i & 63, bb = i >> 6;
        S[bb][rr] = Hj[(size_t)(b0 + bb) * 64 + rr];
    }
    __syncthreads();
    for (int i = tid; i < 4096; i += 256) {
        int bb = i & 63, rr = i >> 6;
        out[(size_t)T_STEPS * B_SZ * NO_SZ + (size_t)(j * 64 + rr) * 256 + b0 + bb] =
            S[bb][rr];
    }
}

// ---------------------------------------------------------------------------
extern "C" void kernel_launch(void* const* d_in, const int* in_sizes, int n_in,
                              void* d_out, int out_size)
{
    const float* X  = nullptr;
    const float* Wi = nullptr;
    const float* Wh = nullptr;
    const float* Wo = nullptr;
    for (int i = 0; i < n_in; i++) {
        switch (in_sizes[i]) {
            case 512 * 256 * 128: X  = (const float*)d_in[i]; break;
            case 512 * 129:       Wi = (const float*)d_in[i]; break;
            case 512 * 513:       Wh = (const float*)d_in[i]; break;
            case 128 * 513:       Wo = (const float*)d_in[i]; break;
            default: break;
        }
    }
    float* out = (float*)d_out;

    g0_kernel<<<dim3(1020, 4), 256>>>(X, Wi, Wh);

    seq_kernel<7><<<128, 128>>>(Wh);
    proj_kernel<<<dim3(4, 4, 9), 256>>>(Wh, Wo, out, 7);
    seq_kernel<6><<<128, 128>>>(Wh);
    proj_kernel<<<dim3(8, 4, 8), 256>>>(Wh, Wo, out, 6);
    seq_kernel<5><<<128, 128>>>(Wh);
    proj_kernel<<<dim3(16, 4, 7), 256>>>(Wh, Wo, out, 5);
    seq_kernel<4><<<128, 128>>>(Wh);
    proj_kernel<<<dim3(32, 4, 6), 256>>>(Wh, Wo, out, 4);
    seq_kernel<3><<<128, 128>>>(Wh);
    proj_kernel<<<dim3(64, 4, 5), 256>>>(Wh, Wo, out, 3);
    seq_kernel<2><<<128, 128>>>(Wh);
    proj_kernel<<<dim3(128, 4, 4), 256>>>(Wh, Wo, out, 2);
    seq_kernel<1><<<128, 128>>>(Wh);
    proj_kernel<<<dim3(256, 4, 3), 256>>>(Wh, Wo, out, 1);
    seq_kernel<0><<<128, 128>>>(Wh);
    proj_kernel<<<dim3(512, 4, 2), 256>>>(Wh, Wo, out, 0);

    finalH_kernel<<<dim3(8, 4), 256>>>(out);
}

// round 8
// speedup vs baseline: 2.6264x; 1.0247x over previous
#include <cuda_runtime.h>
#include <cuda_bf16.h>
#include <cstdint>
#include <cstddef>

#define T_STEPS 512
#define B_SZ    256
#define NO_SZ   128

// ---------------------------------------------------------------------------
// Static scratch.
//   g_G   [tile][b(256)][r(64)]    tile = hep_base(c)+m   (input+bias preacts)
//   g_Hep [tile][b(256)][k(64)]    hidden epochs
//   g_R   [tile][b(256)][o(128)]   prefix-summed output projections
//   g_C   [ctile][b(256)][r(64)]   off-diagonal recurrent projections
// ---------------------------------------------------------------------------
__device__ float g_G  [1020u * 64  * 256];
__device__ float g_Hep[1020u * 64  * 256];
__device__ float g_R  [1020u * 128 * 256];
__device__ float g_C  [988u  * 64  * 256];

__device__ __constant__ int c_S[8] = {0, 0, 256, 512, 704, 832, 912, 960};

__device__ __forceinline__ int hb(int j) { return 1024 - (1024 >> j); }

__device__ __forceinline__ float ftanh(float x) {
    float t = __expf(2.0f * x);
    return 1.0f - __fdividef(2.0f, t + 1.0f);
}

// ---------------------------------------------------------------------------
// bf16 MMA m16n8k16 (row.col, f32 accum)
// ---------------------------------------------------------------------------
__device__ __forceinline__ void mma_bf16(float* d, const uint32_t* a, const uint32_t* b)
{
    asm volatile(
        "mma.sync.aligned.m16n8k16.row.col.f32.bf16.bf16.f32 "
        "{%0,%1,%2,%3},{%4,%5,%6,%7},{%8,%9},{%0,%1,%2,%3};\n"
        : "+f"(d[0]), "+f"(d[1]), "+f"(d[2]), "+f"(d[3])
        : "r"(a[0]), "r"(a[1]), "r"(a[2]), "r"(a[3]), "r"(b[0]), "r"(b[1]));
}

__device__ __forceinline__ uint32_t pack2(float x0, float x1, bool lo)
{
    __nv_bfloat16 h0 = __float2bfloat16(x0);
    __nv_bfloat16 h1 = __float2bfloat16(x1);
    if (lo) {
        h0 = __float2bfloat16(x0 - __bfloat162float(h0));
        h1 = __float2bfloat16(x1 - __bfloat162float(h1));
    }
    __nv_bfloat162 p = __halves2bfloat162(h0, h1);
    return *reinterpret_cast<uint32_t*>(&p);
}

// Shared layout (uint32 words), total 9216 words = 36864 B:
//   AH [64][36] @0   AL [64][36] @2304   BH [64][36] @4608   BL [64][36] @6912
//   S  (float [64][68]) overlays BH/BL region (@4608, 4352 floats <= 4608)
#define AH_OFF 0
#define AL_OFF 2304
#define BH_OFF 4608
#define BL_OFF 6912

// Stage A (64 rows x 64 k, row-major lda) and B (64 cols x 64 k, k-contig ldb).
// koff applies to BOTH A and B k-indices; pass base (unoffset) pointers.
__device__ __forceinline__ void stage_AB(uint32_t* su,
                                         const float* __restrict__ Ag, int lda, int koff,
                                         const float* __restrict__ Bg, int ldb,
                                         int tid)
{
    for (int idx = tid; idx < 64 * 32; idx += 256) {
        int r = idx >> 5, p = idx & 31;
        float x0 = Ag[(size_t)r * lda + koff + 2 * p];
        float x1 = Ag[(size_t)r * lda + koff + 2 * p + 1];
        su[AH_OFF + r * 36 + p] = pack2(x0, x1, false);
        su[AL_OFF + r * 36 + p] = pack2(x0, x1, true);
    }
    for (int idx = tid; idx < 64 * 16; idx += 256) {
        int c = idx >> 4, q = idx & 15;
        float4 v = *(const float4*)&Bg[(size_t)c * ldb + koff + 4 * q];
        su[BH_OFF + c * 36 + 2 * q]     = pack2(v.x, v.y, false);
        su[BL_OFF + c * 36 + 2 * q]     = pack2(v.x, v.y, true);
        su[BH_OFF + c * 36 + 2 * q + 1] = pack2(v.z, v.w, false);
        su[BL_OFF + c * 36 + 2 * q + 1] = pack2(v.z, v.w, true);
    }
}

// 64x64 tile MMA: warp w -> rows (w&3)*16.., cols (w>>2)*32..; acc[4][4]
__device__ __forceinline__ void mma_block(const uint32_t* su, int warp, int lane,
                                          float (&acc)[4][4])
{
    const int mrow = (warp & 3) * 16;
    const int nb   = (warp >> 2) * 32;
    const int gr   = lane >> 2, tg = lane & 3;
#pragma unroll
    for (int c = 0; c < 4; c++) {
        const int pb = c * 8;
        uint32_t ah[4], al[4];
        ah[0] = su[AH_OFF + (mrow + gr)     * 36 + pb + tg];
        ah[1] = su[AH_OFF + (mrow + gr + 8) * 36 + pb + tg];
        ah[2] = su[AH_OFF + (mrow + gr)     * 36 + pb + 4 + tg];
        ah[3] = su[AH_OFF + (mrow + gr + 8) * 36 + pb + 4 + tg];
        al[0] = su[AL_OFF + (mrow + gr)     * 36 + pb + tg];
        al[1] = su[AL_OFF + (mrow + gr + 8) * 36 + pb + tg];
        al[2] = su[AL_OFF + (mrow + gr)     * 36 + pb + 4 + tg];
        al[3] = su[AL_OFF + (mrow + gr + 8) * 36 + pb + 4 + tg];
#pragma unroll
        for (int nt = 0; nt < 4; nt++) {
            const int colb = nb + nt * 8 + gr;
            uint32_t bh[2], bl[2];
            bh[0] = su[BH_OFF + colb * 36 + pb + tg];
            bh[1] = su[BH_OFF + colb * 36 + pb + 4 + tg];
            bl[0] = su[BL_OFF + colb * 36 + pb + tg];
            bl[1] = su[BL_OFF + colb * 36 + pb + 4 + tg];
            mma_bf16(acc[nt], ah, bh);
            mma_bf16(acc[nt], ah, bl);
            mma_bf16(acc[nt], al, bh);
        }
    }
}

// acc -> S[col][row] transpose staging (S overlays B smem region)
__device__ __forceinline__ void acc_to_S(float* Sf, int warp, int lane, float (&acc)[4][4])
{
    const int mrow = (warp & 3) * 16;
    const int nb   = (warp >> 2) * 32;
    const int gr   = lane >> 2, tg = lane & 3;
#pragma unroll
    for (int nt = 0; nt < 4; nt++) {
        const int c0 = nb + nt * 8 + 2 * tg;
        Sf[(size_t)c0       * 68 + mrow + gr]     = acc[nt][0];
        Sf[(size_t)(c0 + 1) * 68 + mrow + gr]     = acc[nt][1];
        Sf[(size_t)c0       * 68 + mrow + gr + 8] = acc[nt][2];
        Sf[(size_t)(c0 + 1) * 68 + mrow + gr + 8] = acc[nt][3];
    }
}

// ---------------------------------------------------------------------------
// g0: G[c][m] = Wi_c @ x_{m<<c} + (Wi_bias + Wh_bias).
// grid (ntiles, 4), 256 thr; tile index = idx0 + blockIdx.x.
// ---------------------------------------------------------------------------
__global__ void __launch_bounds__(256) g0_kernel(const float* __restrict__ X,
                                                 const float* __restrict__ Wi,
                                                 const float* __restrict__ Wh,
                                                 int idx0)
{
    __shared__ __align__(16) uint32_t su[9216];
    float* Sf = (float*)(su + BH_OFF);

    const int idx = idx0 + blockIdx.x;
    const int v   = 1024 - idx;
    const int c   = __clz(v - 1) - 22;
    const int m   = idx - (1024 - (1024 >> c));
    const int t   = m << c;
    const int b0  = blockIdx.y * 64;
    const int tid = threadIdx.x;
    const int warp = tid >> 5, lane = tid & 31;

    const float* Ag = Wi + (size_t)(c * 64) * 129;
    const float* Bg = X + ((size_t)t * 256 + b0) * 128;

    float acc[4][4];
#pragma unroll
    for (int q = 0; q < 4; q++)
#pragma unroll
        for (int u = 0; u < 4; u++) acc[q][u] = 0.f;

    for (int kh = 0; kh < 2; kh++) {
        stage_AB(su, Ag, 129, kh * 64, Bg, 128, tid);
        __syncthreads();
        mma_block(su, warp, lane, acc);
        __syncthreads();
    }

    {
        const int mrow = (warp & 3) * 16, gr = lane >> 2;
        int r0 = c * 64 + mrow + gr, r1 = r0 + 8;
        float ba = Wi[(size_t)r0 * 129 + 128] + Wh[(size_t)r0 * 513 + 512];
        float bb = Wi[(size_t)r1 * 129 + 128] + Wh[(size_t)r1 * 513 + 512];
#pragma unroll
        for (int nt = 0; nt < 4; nt++) {
            acc[nt][0] += ba; acc[nt][1] += ba;
            acc[nt][2] += bb; acc[nt][3] += bb;
        }
    }

    acc_to_S(Sf, warp, lane, acc);
    __syncthreads();

    float* out = g_G + (size_t)idx * 16384 + (size_t)b0 * 64;
    for (int i = tid; i < 64 * 16; i += 256) {
        int col = i >> 4, rq = i & 15;
        *(float4*)&out[(size_t)col * 64 + rq * 4] = *(float4*)&Sf[(size_t)col * 68 + rq * 4];
    }
}

// ---------------------------------------------------------------------------
// projC: C[z][j][e] = Wh[z-rows, j-cols] @ H_j[e],  z = zbase + blockIdx.z.
// grid (U_j, 4, nz), 256 threads.
// ---------------------------------------------------------------------------
__global__ void __launch_bounds__(256) projC_kernel(const float* __restrict__ Wh,
                                                    int j, int zbase)
{
    __shared__ __align__(16) uint32_t su[9216];
    float* Sf = (float*)(su + BH_OFF);

    const int e   = blockIdx.x;
    const int U   = gridDim.x;
    const int b0  = blockIdx.y * 64;
    const int z   = zbase + blockIdx.z;
    const int tid = threadIdx.x;
    const int warp = tid >> 5, lane = tid & 31;

    const float* Ag = Wh + (size_t)(z * 64) * 513 + j * 64;
    const float* Bg = g_Hep + (size_t)(hb(j) + e) * 16384 + (size_t)b0 * 64;

    float acc[4][4];
#pragma unroll
    for (int q = 0; q < 4; q++)
#pragma unroll
        for (int u = 0; u < 4; u++) acc[q][u] = 0.f;

    stage_AB(su, Ag, 513, 0, Bg, 64, tid);
    __syncthreads();
    mma_block(su, warp, lane, acc);
    __syncthreads();
    acc_to_S(Sf, warp, lane, acc);
    __syncthreads();

    float* out = g_C + (size_t)(c_S[j] + z * U + e) * 16384 + (size_t)b0 * 64;
    for (int i = tid; i < 64 * 16; i += 256) {
        int col = i >> 4, rq = i & 15;
        *(float4*)&out[(size_t)col * 64 + rq * 4] =
            *(float4*)&Sf[(size_t)col * 68 + rq * 4];
    }
}

// ---------------------------------------------------------------------------
// projR: R_j[e] rows z*64.. = Wo[rows, j-cols] @ H_j[e] + R_{j+1}[e>>1]
//        (+Wo bias at j=7; tanh->Y at j=0).  Off critical path (stream s2).
// grid (U_j, 4, 2), 256 threads.
// ---------------------------------------------------------------------------
__global__ void __launch_bounds__(256) projR_kernel(const float* __restrict__ Wo,
                                                    float* __restrict__ Y, int j)
{
    __shared__ __align__(16) uint32_t su[9216];
    float* Sf = (float*)(su + BH_OFF);

    const int e   = blockIdx.x;
    const int b0  = blockIdx.y * 64;
    const int z   = blockIdx.z;
    const int tid = threadIdx.x;
    const int warp = tid >> 5, lane = tid & 31;

    const float* Ag = Wo + (size_t)(z * 64) * 513 + j * 64;
    const float* Bg = g_Hep + (size_t)(hb(j) + e) * 16384 + (size_t)b0 * 64;

    float acc[4][4];
#pragma unroll
    for (int q = 0; q < 4; q++)
#pragma unroll
        for (int u = 0; u < 4; u++) acc[q][u] = 0.f;

    stage_AB(su, Ag, 513, 0, Bg, 64, tid);
    __syncthreads();
    mma_block(su, warp, lane, acc);
    __syncthreads();
    acc_to_S(Sf, warp, lane, acc);
    __syncthreads();

    const int o0 = z * 64;
    const float* Rpar = (j < 7)
        ? g_R + (size_t)(hb(j + 1) + (e >> 1)) * 32768
        : nullptr;
    for (int i = tid; i < 64 * 16; i += 256) {
        int col = i >> 4, rq = i & 15;
        float4 s = *(float4*)&Sf[(size_t)col * 68 + rq * 4];
        if (j < 7) {
            float4 p = *(const float4*)&Rpar[(size_t)(b0 + col) * 128 + o0 + rq * 4];
            s.x += p.x; s.y += p.y; s.z += p.z; s.w += p.w;
        } else {
            s.x += Wo[(size_t)(o0 + rq * 4 + 0) * 513 + 512];
            s.y += Wo[(size_t)(o0 + rq * 4 + 1) * 513 + 512];
            s.z += Wo[(size_t)(o0 + rq * 4 + 2) * 513 + 512];
            s.w += Wo[(size_t)(o0 + rq * 4 + 3) * 513 + 512];
        }
        if (j == 0) {
            float4 y = make_float4(ftanh(s.x), ftanh(s.y), ftanh(s.z), ftanh(s.w));
            *(float4*)&Y[((size_t)e * 256 + b0 + col) * 128 + o0 + rq * 4] = y;
        } else {
            *(float4*)&g_R[(size_t)(hb(j) + e) * 32768 +
                           (size_t)(b0 + col) * 128 + o0 + rq * 4] = s;
        }
    }
}

// ---------------------------------------------------------------------------
// seq<C>: H[m] = tanh(G[m] + sum_{j>C} C[C][j][(m-1)>>(j-C)] + W_CC @ H[m-1])
// grid 128 CTAs x 2 batch cols, 128 threads (thread = (col, full 64-dot row)).
// ---------------------------------------------------------------------------
template <int NS>
__device__ __forceinline__ void fetchv(float (&dst)[NS], int m, int U,
                                       const float* __restrict__ Gb,
                                       const float* const (&Cb)[NS], int off)
{
    if (m >= U) return;
    dst[0] = Gb[(size_t)m * 16384 + off];
    if (m > 0) {
#pragma unroll
        for (int s = 1; s < NS; s++)
            dst[s] = Cb[s][(size_t)((m - 1) >> s) * 16384 + off];
    }
}

template <int C>
__global__ void __launch_bounds__(128) seq_kernel(const float* __restrict__ Wh)
{
    constexpr int U  = 512 >> C;
    constexpr int NS = (C == 7) ? 1 : (8 - C);
    constexpr int HB = 1024 - (1024 >> C);
    constexpr int csl[8] = {0, 0, 256, 512, 704, 832, 912, 960};

    const int tid = threadIdx.x;
    const int lb  = tid >> 6;
    const int r   = tid & 63;
    const int b   = blockIdx.x * 2 + lb;
    const int off = b * 64 + r;

    __shared__ float Ws[64][65];
    __shared__ float Hs[2][2][64];

    for (int i = tid; i < 4096; i += 128)
        Ws[i >> 6][i & 63] = Wh[(size_t)(C * 64 + (i >> 6)) * 513 + C * 64 + (i & 63)];
    __syncthreads();

    float w[64];
#pragma unroll
    for (int q = 0; q < 64; q++) w[q] = Ws[r][q];

    const float* Gb = g_G + (size_t)HB * 16384;
    float*       Hbp = g_Hep + (size_t)HB * 16384;
    const float* Cb[NS];
    Cb[0] = nullptr;
#pragma unroll
    for (int s = 1; s < NS; s++)
        Cb[s] = g_C + (size_t)(csl[C + s] + C * (512 >> (C + s))) * 16384;

    auto step = [&](int m, const float (&vv)[NS]) {
        const int rb = m & 1;
        float a = vv[0];
        if (m > 0) {
            float a0 = 0.f, a1 = 0.f, a2 = 0.f, a3 = 0.f;
#pragma unroll
            for (int q = 0; q < 64; q += 4) {
                float4 hv = *(const float4*)&Hs[rb][lb][q];
                a0 += w[q + 0] * hv.x;
                a1 += w[q + 1] * hv.y;
                a2 += w[q + 2] * hv.z;
                a3 += w[q + 3] * hv.w;
            }
            a += (a0 + a1) + (a2 + a3);
#pragma unroll
            for (int s = 1; s < NS; s++) a += vv[s];
        }
        float h = ftanh(a);
        Hbp[(size_t)m * 16384 + off] = h;
        Hs[rb ^ 1][lb][r] = h;
        __syncthreads();
    };

    float v0[NS], v1[NS], v2[NS], v3[NS];
    fetchv<NS>(v0, 0, U, Gb, Cb, off);
    fetchv<NS>(v1, 1, U, Gb, Cb, off);
    fetchv<NS>(v2, 2, U, Gb, Cb, off);
    fetchv<NS>(v3, 3, U, Gb, Cb, off);

    for (int m = 0; m < U; m += 4) {
        step(m + 0, v0); fetchv<NS>(v0, m + 4, U, Gb, Cb, off);
        step(m + 1, v1); fetchv<NS>(v1, m + 5, U, Gb, Cb, off);
        step(m + 2, v2); fetchv<NS>(v2, m + 6, U, Gb, Cb, off);
        step(m + 3, v3); fetchv<NS>(v3, m + 7, U, Gb, Cb, off);
    }
}

// ---------------------------------------------------------------------------
// final H: out[T*B*NO + (j*64+r)*256 + b] = H_j[last epoch][b][r] (transpose)
// ---------------------------------------------------------------------------
__global__ void __launch_bounds__(256) finalH_kernel(float* __restrict__ out)
{
    __shared__ float S[64][65];
    const int j   = blockIdx.x;
    const int b0  = blockIdx.y * 64;
    const int tid = threadIdx.x;
    const int e   = (512 >> j) - 1;
    const float* Hj = g_Hep + (size_t)(hb(j) + e) * 16384;

    for (int i = tid; i < 4096; i += 256) {
        int rr = i & 63, bb = i >> 6;
        S[bb][rr] = Hj[(size_t)(b0 + bb) * 64 + rr];
    }
    __syncthreads();
    for (int i = tid; i < 4096; i += 256) {
        int bb = i & 63, rr = i >> 6;
        out[(size_t)T_STEPS * B_SZ * NO_SZ + (size_t)(j * 64 + rr) * 256 + b0 + bb] =
            S[bb][rr];
    }
}

// ---------------------------------------------------------------------------
// Launch.  Multi-stream fork/join when streams are available; otherwise
// fall back to the known-good single-stream chain (R6 ordering).
//   main: g0_hi -> seq<j> -> projC(urgent z=j-1) -> ...
//   s1  : g0_lo (levels 3..0)              join before seq<3>
//   s2  : projR chain (R_7..R_0 -> Y)      join at end
//   s3  : projC deferred (z<=j-2)          join before seq<z> via evD[z+2]
// ---------------------------------------------------------------------------
static cudaStream_t s_s1 = nullptr, s_s2 = nullptr, s_s3 = nullptr;
static cudaEvent_t  s_ev0, s_evG0, s_evH[8], s_evR0, s_evD[8];
static int s_state = 0;  // 0=uninit, 1=ok, -1=failed

static bool ensure_streams()
{
    if (s_state) return s_state > 0;
    bool ok = true;
    ok &= cudaStreamCreateWithFlags(&s_s1, cudaStreamNonBlocking) == cudaSuccess;
    ok &= cudaStreamCreateWithFlags(&s_s2, cudaStreamNonBlocking) == cudaSuccess;
    ok &= cudaStreamCreateWithFlags(&s_s3, cudaStreamNonBlocking) == cudaSuccess;
    ok &= cudaEventCreateWithFlags(&s_ev0,  cudaEventDisableTiming) == cudaSuccess;
    ok &= cudaEventCreateWithFlags(&s_evG0, cudaEventDisableTiming) == cudaSuccess;
    ok &= cudaEventCreateWithFlags(&s_evR0, cudaEventDisableTiming) == cudaSuccess;
    for (int i = 0; i < 8; i++) {
        ok &= cudaEventCreateWithFlags(&s_evH[i], cudaEventDisableTiming) == cudaSuccess;
        ok &= cudaEventCreateWithFlags(&s_evD[i], cudaEventDisableTiming) == cudaSuccess;
    }
    s_state = ok ? 1 : -1;
    return ok;
}

extern "C" void kernel_launch(void* const* d_in, const int* in_sizes, int n_in,
                              void* d_out, int out_size)
{
    const float* X  = nullptr;
    const float* Wi = nullptr;
    const float* Wh = nullptr;
    const float* Wo = nullptr;
    for (int i = 0; i < n_in; i++) {
        switch (in_sizes[i]) {
            case 512 * 256 * 128: X  = (const float*)d_in[i]; break;
            case 512 * 129:       Wi = (const float*)d_in[i]; break;
            case 512 * 513:       Wh = (const float*)d_in[i]; break;
            case 128 * 513:       Wo = (const float*)d_in[i]; break;
            default: break;
        }
    }
    float* out = (float*)d_out;

    if (!ensure_streams()) {
        // -------- Fallback: single-stream chain (R6 ordering, known-good) ----
        g0_kernel<<<dim3(1020, 4), 256>>>(X, Wi, Wh, 0);
        seq_kernel<7><<<128, 128>>>(Wh);
        projR_kernel<<<dim3(4, 4, 2), 256>>>(Wo, out, 7);
        projC_kernel<<<dim3(4, 4, 7), 256>>>(Wh, 7, 0);
        seq_kernel<6><<<128, 128>>>(Wh);
        projR_kernel<<<dim3(8, 4, 2), 256>>>(Wo, out, 6);
        projC_kernel<<<dim3(8, 4, 6), 256>>>(Wh, 6, 0);
        seq_kernel<5><<<128, 128>>>(Wh);
        projR_kernel<<<dim3(16, 4, 2), 256>>>(Wo, out, 5);
        projC_kernel<<<dim3(16, 4, 5), 256>>>(Wh, 5, 0);
        seq_kernel<4><<<128, 128>>>(Wh);
        projR_kernel<<<dim3(32, 4, 2), 256>>>(Wo, out, 4);
        projC_kernel<<<dim3(32, 4, 4), 256>>>(Wh, 4, 0);
        seq_kernel<3><<<128, 128>>>(Wh);
        projR_kernel<<<dim3(64, 4, 2), 256>>>(Wo, out, 3);
        projC_kernel<<<dim3(64, 4, 3), 256>>>(Wh, 3, 0);
        seq_kernel<2><<<128, 128>>>(Wh);
        projR_kernel<<<dim3(128, 4, 2), 256>>>(Wo, out, 2);
        projC_kernel<<<dim3(128, 4, 2), 256>>>(Wh, 2, 0);
        seq_kernel<1><<<128, 128>>>(Wh);
        projR_kernel<<<dim3(256, 4, 2), 256>>>(Wo, out, 1);
        projC_kernel<<<dim3(256, 4, 1), 256>>>(Wh, 1, 0);
        seq_kernel<0><<<128, 128>>>(Wh);
        projR_kernel<<<dim3(512, 4, 2), 256>>>(Wo, out, 0);
        finalH_kernel<<<dim3(8, 4), 256>>>(out);
        return;
    }

    cudaStream_t s1 = s_s1, s2 = s_s2, s3 = s_s3;

    // Fork: g0_lo (levels 3..0, tiles 0..959) on s1.
    cudaEventRecord(s_ev0, 0);
    cudaStreamWaitEvent(s1, s_ev0, 0);
    g0_kernel<<<dim3(960, 4), 256, 0, s1>>>(X, Wi, Wh, 0);
    cudaEventRecord(s_evG0, s1);

    // Main: g0_hi (levels 7..4, tiles 960..1019).
    g0_kernel<<<dim3(60, 4), 256>>>(X, Wi, Wh, 960);

    // ---- level 7 ----
    seq_kernel<7><<<128, 128>>>(Wh);
    cudaEventRecord(s_evH[7], 0);
    cudaStreamWaitEvent(s2, s_evH[7], 0);
    projR_kernel<<<dim3(4, 4, 2), 256, 0, s2>>>(Wo, out, 7);
    cudaStreamWaitEvent(s3, s_evH[7], 0);
    projC_kernel<<<dim3(4, 4, 6), 256, 0, s3>>>(Wh, 7, 0);   // deferred z=0..5
    cudaEventRecord(s_evD[7], s3);
    projC_kernel<<<dim3(4, 4, 1), 256>>>(Wh, 7, 6);          // urgent z=6

    // ---- level 6 ----
    seq_kernel<6><<<128, 128>>>(Wh);
    cudaEventRecord(s_evH[6], 0);
    cudaStreamWaitEvent(s2, s_evH[6], 0);
    projR_kernel<<<dim3(8, 4, 2), 256, 0, s2>>>(Wo, out, 6);
    cudaStreamWaitEvent(s3, s_evH[6], 0);
    projC_kernel<<<dim3(8, 4, 5), 256, 0, s3>>>(Wh, 6, 0);   // deferred z=0..4
    cudaEventRecord(s_evD[6], s3);
    projC_kernel<<<dim3(8, 4, 1), 256>>>(Wh, 6, 5);          // urgent z=5

    // ---- level 5 ---- (needs deferred from source 7: evD[7])
    cudaStreamWaitEvent(0, s_evD[7], 0);
    seq_kernel<5><<<128, 128>>>(Wh);
    cudaEventRecord(s_evH[5], 0);
    cudaStreamWaitEvent(s2, s_evH[5], 0);
    projR_kernel<<<dim3(16, 4, 2), 256, 0, s2>>>(Wo, out, 5);
    cudaStreamWaitEvent(s3, s_evH[5], 0);
    projC_kernel<<<dim3(16, 4, 4), 256, 0, s3>>>(Wh, 5, 0);  // deferred z=0..3
    cudaEventRecord(s_evD[5], s3);
    projC_kernel<<<dim3(16, 4, 1), 256>>>(Wh, 5, 4);         // urgent z=4

    // ---- level 4 ----
    cudaStreamWaitEvent(0, s_evD[6], 0);
    seq_kernel<4><<<128, 128>>>(Wh);
    cudaEventRecord(s_evH[4], 0);
    cudaStreamWaitEvent(s2, s_evH[4], 0);
    projR_kernel<<<dim3(32, 4, 2), 256, 0, s2>>>(Wo, out, 4);
    cudaStreamWaitEvent(s3, s_evH[4], 0);
    projC_kernel<<<dim3(32, 4, 3), 256, 0, s3>>>(Wh, 4, 0);  // deferred z=0..2
    cudaEventRecord(s_evD[4], s3);
    projC_kernel<<<dim3(32, 4, 1), 256>>>(Wh, 4, 3);         // urgent z=3

    // ---- level 3 ---- (needs g0_lo and deferred from source 5)
    cudaStreamWaitEvent(0, s_evG0, 0);
    cudaStreamWaitEvent(0, s_evD[5], 0);
    seq_kernel<3><<<128, 128>>>(Wh);
    cudaEventRecord(s_evH[3], 0);
    cudaStreamWaitEvent(s2, s_evH[3], 0);
    projR_kernel<<<dim3(64, 4, 2), 256, 0, s2>>>(Wo, out, 3);
    cudaStreamWaitEvent(s3, s_evH[3], 0);
    projC_kernel<<<dim3(64, 4, 2), 256, 0, s3>>>(Wh, 3, 0);  // deferred z=0..1
    cudaEventRecord(s_evD[3], s3);
    projC_kernel<<<dim3(64, 4, 1), 256>>>(Wh, 3, 2);         // urgent z=2

    // ---- level 2 ----
    cudaStreamWaitEvent(0, s_evD[4], 0);
    seq_kernel<2><<<128, 128>>>(Wh);
    cudaEventRecord(s_evH[2], 0);
    cudaStreamWaitEvent(s2, s_evH[2], 0);
    projR_kernel<<<dim3(128, 4, 2), 256, 0, s2>>>(Wo, out, 2);
    cudaStreamWaitEvent(s3, s_evH[2], 0);
    projC_kernel<<<dim3(128, 4, 1), 256, 0, s3>>>(Wh, 2, 0); // deferred z=0
    cudaEventRecord(s_evD[2], s3);
    projC_kernel<<<dim3(128, 4, 1), 256>>>(Wh, 2, 1);        // urgent z=1

    // ---- level 1 ----
    cudaStreamWaitEvent(0, s_evD[3], 0);
    seq_kernel<1><<<128, 128>>>(Wh);
    cudaEventRecord(s_evH[1], 0);
    cudaStreamWaitEvent(s2, s_evH[1], 0);
    projR_kernel<<<dim3(256, 4, 2), 256, 0, s2>>>(Wo, out, 1);
    projC_kernel<<<dim3(256, 4, 1), 256>>>(Wh, 1, 0);        // urgent z=0 (only)

    // ---- level 0 ----
    cudaStreamWaitEvent(0, s_evD[2], 0);
    seq_kernel<0><<<128, 128>>>(Wh);
    cudaEventRecord(s_evH[0], 0);
    cudaStreamWaitEvent(s2, s_evH[0], 0);
    projR_kernel<<<dim3(512, 4, 2), 256, 0, s2>>>(Wo, out, 0);  // writes Y
    cudaEventRecord(s_evR0, s2);

    finalH_kernel<<<dim3(8, 4), 256>>>(out);

    // Join remaining branches into main stream before capture ends.
    cudaStreamWaitEvent(0, s_evR0, 0);
}

// round 9
// speedup vs baseline: 2.9666x; 1.1295x over previous
#include <cuda_runtime.h>
#include <cuda_bf16.h>
#include <cstdint>
#include <cstddef>

#define T_STEPS 512
#define B_SZ    256
#define NO_SZ   128

// ---------------------------------------------------------------------------
// Static scratch.
//   g_G   [tile][b(256)][r(64)]    tile = hep_base(c)+m  (preacts; gsum folds
//                                   slow C streams in place -> G')
//   g_Hep [tile][b(256)][k(64)]    hidden epochs
//   g_R   [tile][b(256)][o(128)]   prefix-summed output projections
//   g_C   [ctile][b(256)][r(64)]   off-diagonal recurrent projections
// ---------------------------------------------------------------------------
__device__ float g_G  [1020u * 64  * 256];
__device__ float g_Hep[1020u * 64  * 256];
__device__ float g_R  [1020u * 128 * 256];
__device__ float g_C  [988u  * 64  * 256];

__device__ __constant__ int c_S[8] = {0, 0, 256, 512, 704, 832, 912, 960};

__device__ __forceinline__ int hb(int j) { return 1024 - (1024 >> j); }

__device__ __forceinline__ float ftanh(float x) {
    float t = __expf(2.0f * x);
    return 1.0f - __fdividef(2.0f, t + 1.0f);
}

// ---------------------------------------------------------------------------
// bf16 MMA m16n8k16 (row.col, f32 accum)
// ---------------------------------------------------------------------------
__device__ __forceinline__ void mma_bf16(float* d, const uint32_t* a, const uint32_t* b)
{
    asm volatile(
        "mma.sync.aligned.m16n8k16.row.col.f32.bf16.bf16.f32 "
        "{%0,%1,%2,%3},{%4,%5,%6,%7},{%8,%9},{%0,%1,%2,%3};\n"
        : "+f"(d[0]), "+f"(d[1]), "+f"(d[2]), "+f"(d[3])
        : "r"(a[0]), "r"(a[1]), "r"(a[2]), "r"(a[3]), "r"(b[0]), "r"(b[1]));
}

__device__ __forceinline__ uint32_t pack2(float x0, float x1, bool lo)
{
    __nv_bfloat16 h0 = __float2bfloat16(x0);
    __nv_bfloat16 h1 = __float2bfloat16(x1);
    if (lo) {
        h0 = __float2bfloat16(x0 - __bfloat162float(h0));
        h1 = __float2bfloat16(x1 - __bfloat162float(h1));
    }
    __nv_bfloat162 p = __halves2bfloat162(h0, h1);
    return *reinterpret_cast<uint32_t*>(&p);
}

// Shared layout (uint32 words), total 9216 words = 36864 B:
//   AH [64][36] @0   AL [64][36] @2304   BH [64][36] @4608   BL [64][36] @6912
//   S  (float [64][68]) overlays BH/BL region (@4608, 4352 floats <= 4608)
#define AH_OFF 0
#define AL_OFF 2304
#define BH_OFF 4608
#define BL_OFF 6912

// Stage A (64 rows x 64 k, row-major lda) and B (64 cols x 64 k, k-contig ldb).
// koff applies to BOTH A and B k-indices; pass base (unoffset) pointers.
__device__ __forceinline__ void stage_AB(uint32_t* su,
                                         const float* __restrict__ Ag, int lda, int koff,
                                         const float* __restrict__ Bg, int ldb,
                                         int tid)
{
    for (int idx = tid; idx < 64 * 32; idx += 256) {
        int r = idx >> 5, p = idx & 31;
        float x0 = Ag[(size_t)r * lda + koff + 2 * p];
        float x1 = Ag[(size_t)r * lda + koff + 2 * p + 1];
        su[AH_OFF + r * 36 + p] = pack2(x0, x1, false);
        su[AL_OFF + r * 36 + p] = pack2(x0, x1, true);
    }
    for (int idx = tid; idx < 64 * 16; idx += 256) {
        int c = idx >> 4, q = idx & 15;
        float4 v = *(const float4*)&Bg[(size_t)c * ldb + koff + 4 * q];
        su[BH_OFF + c * 36 + 2 * q]     = pack2(v.x, v.y, false);
        su[BL_OFF + c * 36 + 2 * q]     = pack2(v.x, v.y, true);
        su[BH_OFF + c * 36 + 2 * q + 1] = pack2(v.z, v.w, false);
        su[BL_OFF + c * 36 + 2 * q + 1] = pack2(v.z, v.w, true);
    }
}

// 64x64 tile MMA: warp w -> rows (w&3)*16.., cols (w>>2)*32..; acc[4][4]
__device__ __forceinline__ void mma_block(const uint32_t* su, int warp, int lane,
                                          float (&acc)[4][4])
{
    const int mrow = (warp & 3) * 16;
    const int nb   = (warp >> 2) * 32;
    const int gr   = lane >> 2, tg = lane & 3;
#pragma unroll
    for (int c = 0; c < 4; c++) {
        const int pb = c * 8;
        uint32_t ah[4], al[4];
        ah[0] = su[AH_OFF + (mrow + gr)     * 36 + pb + tg];
        ah[1] = su[AH_OFF + (mrow + gr + 8) * 36 + pb + tg];
        ah[2] = su[AH_OFF + (mrow + gr)     * 36 + pb + 4 + tg];
        ah[3] = su[AH_OFF + (mrow + gr + 8) * 36 + pb + 4 + tg];
        al[0] = su[AL_OFF + (mrow + gr)     * 36 + pb + tg];
        al[1] = su[AL_OFF + (mrow + gr + 8) * 36 + pb + tg];
        al[2] = su[AL_OFF + (mrow + gr)     * 36 + pb + 4 + tg];
        al[3] = su[AL_OFF + (mrow + gr + 8) * 36 + pb + 4 + tg];
#pragma unroll
        for (int nt = 0; nt < 4; nt++) {
            const int colb = nb + nt * 8 + gr;
            uint32_t bh[2], bl[2];
            bh[0] = su[BH_OFF + colb * 36 + pb + tg];
            bh[1] = su[BH_OFF + colb * 36 + pb + 4 + tg];
            bl[0] = su[BL_OFF + colb * 36 + pb + tg];
            bl[1] = su[BL_OFF + colb * 36 + pb + 4 + tg];
            mma_bf16(acc[nt], ah, bh);
            mma_bf16(acc[nt], ah, bl);
            mma_bf16(acc[nt], al, bh);
        }
    }
}

// acc -> S[col][row] transpose staging (S overlays B smem region)
__device__ __forceinline__ void acc_to_S(float* Sf, int warp, int lane, float (&acc)[4][4])
{
    const int mrow = (warp & 3) * 16;
    const int nb   = (warp >> 2) * 32;
    const int gr   = lane >> 2, tg = lane & 3;
#pragma unroll
    for (int nt = 0; nt < 4; nt++) {
        const int c0 = nb + nt * 8 + 2 * tg;
        Sf[(size_t)c0       * 68 + mrow + gr]     = acc[nt][0];
        Sf[(size_t)(c0 + 1) * 68 + mrow + gr]     = acc[nt][1];
        Sf[(size_t)c0       * 68 + mrow + gr + 8] = acc[nt][2];
        Sf[(size_t)(c0 + 1) * 68 + mrow + gr + 8] = acc[nt][3];
    }
}

// ---------------------------------------------------------------------------
// g0: G[c][m] = Wi_c @ x_{m<<c} + (Wi_bias + Wh_bias).
// grid (ntiles, 4), 256 thr; tile index = idx0 + blockIdx.x.
// ---------------------------------------------------------------------------
__global__ void __launch_bounds__(256) g0_kernel(const float* __restrict__ X,
                                                 const float* __restrict__ Wi,
                                                 const float* __restrict__ Wh,
                                                 int idx0)
{
    __shared__ __align__(16) uint32_t su[9216];
    float* Sf = (float*)(su + BH_OFF);

    const int idx = idx0 + blockIdx.x;
    const int v   = 1024 - idx;
    const int c   = __clz(v - 1) - 22;
    const int m   = idx - (1024 - (1024 >> c));
    const int t   = m << c;
    const int b0  = blockIdx.y * 64;
    const int tid = threadIdx.x;
    const int warp = tid >> 5, lane = tid & 31;

    const float* Ag = Wi + (size_t)(c * 64) * 129;
    const float* Bg = X + ((size_t)t * 256 + b0) * 128;

    float acc[4][4];
#pragma unroll
    for (int q = 0; q < 4; q++)
#pragma unroll
        for (int u = 0; u < 4; u++) acc[q][u] = 0.f;

    for (int kh = 0; kh < 2; kh++) {
        stage_AB(su, Ag, 129, kh * 64, Bg, 128, tid);
        __syncthreads();
        mma_block(su, warp, lane, acc);
        __syncthreads();
    }

    {
        const int mrow = (warp & 3) * 16, gr = lane >> 2;
        int r0 = c * 64 + mrow + gr, r1 = r0 + 8;
        float ba = Wi[(size_t)r0 * 129 + 128] + Wh[(size_t)r0 * 513 + 512];
        float bb = Wi[(size_t)r1 * 129 + 128] + Wh[(size_t)r1 * 513 + 512];
#pragma unroll
        for (int nt = 0; nt < 4; nt++) {
            acc[nt][0] += ba; acc[nt][1] += ba;
            acc[nt][2] += bb; acc[nt][3] += bb;
        }
    }

    acc_to_S(Sf, warp, lane, acc);
    __syncthreads();

    float* out = g_G + (size_t)idx * 16384 + (size_t)b0 * 64;
    for (int i = tid; i < 64 * 16; i += 256) {
        int col = i >> 4, rq = i & 15;
        *(float4*)&out[(size_t)col * 64 + rq * 4] = *(float4*)&Sf[(size_t)col * 68 + rq * 4];
    }
}

// ---------------------------------------------------------------------------
// projC: C[z][j][e] = Wh[z-rows, j-cols] @ H_j[e],  z = zbase + blockIdx.z.
// grid (U_j, 4, nz), 256 threads.
// ---------------------------------------------------------------------------
__global__ void __launch_bounds__(256) projC_kernel(const float* __restrict__ Wh,
                                                    int j, int zbase)
{
    __shared__ __align__(16) uint32_t su[9216];
    float* Sf = (float*)(su + BH_OFF);

    const int e   = blockIdx.x;
    const int U   = gridDim.x;
    const int b0  = blockIdx.y * 64;
    const int z   = zbase + blockIdx.z;
    const int tid = threadIdx.x;
    const int warp = tid >> 5, lane = tid & 31;

    const float* Ag = Wh + (size_t)(z * 64) * 513 + j * 64;
    const float* Bg = g_Hep + (size_t)(hb(j) + e) * 16384 + (size_t)b0 * 64;

    float acc[4][4];
#pragma unroll
    for (int q = 0; q < 4; q++)
#pragma unroll
        for (int u = 0; u < 4; u++) acc[q][u] = 0.f;

    stage_AB(su, Ag, 513, 0, Bg, 64, tid);
    __syncthreads();
    mma_block(su, warp, lane, acc);
    __syncthreads();
    acc_to_S(Sf, warp, lane, acc);
    __syncthreads();

    float* out = g_C + (size_t)(c_S[j] + z * U + e) * 16384 + (size_t)b0 * 64;
    for (int i = tid; i < 64 * 16; i += 256) {
        int col = i >> 4, rq = i & 15;
        *(float4*)&out[(size_t)col * 64 + rq * 4] =
            *(float4*)&Sf[(size_t)col * 68 + rq * 4];
    }
}

// ---------------------------------------------------------------------------
// gsum: fold slow C streams into G in place (per level C, epochs m >= 1):
//   G'[m] = G[m] + sum_{j >= C+2} C[C][j][(m-1)>>(j-C)]
// grid (U_C - 1, 4), 256 threads; m = blockIdx.x + 1.  Off critical path.
// ---------------------------------------------------------------------------
__global__ void __launch_bounds__(256) gsum_kernel(int C)
{
    const int m   = blockIdx.x + 1;
    const int b0  = blockIdx.y * 64;
    const int tid = threadIdx.x;
    const int HB  = 1024 - (1024 >> C);

    float* Gt = g_G + (size_t)(HB + m) * 16384 + (size_t)b0 * 64;

    // collect source tile pointers
    const float* Ct[6];
    int ns = 0;
    for (int j = C + 2; j < 8; j++) {
        int e = (m - 1) >> (j - C);
        Ct[ns++] = g_C + (size_t)(c_S[j] + C * (512 >> j) + e) * 16384 + (size_t)b0 * 64;
    }

    for (int i = tid; i < 1024; i += 256) {
        float4 a = *(float4*)&Gt[i * 4];
        for (int s = 0; s < ns; s++) {
            float4 v = *(const float4*)&Ct[s][i * 4];
            a.x += v.x; a.y += v.y; a.z += v.z; a.w += v.w;
        }
        *(float4*)&Gt[i * 4] = a;
    }
}

// ---------------------------------------------------------------------------
// projR: R_j[e] rows z*64.. = Wo[rows, j-cols] @ H_j[e] + R_{j+1}[e>>1]
//        (+Wo bias at j=7; tanh->Y at j=0).  Off critical path (stream s2).
// grid (U_j, 4, 2), 256 threads.
// ---------------------------------------------------------------------------
__global__ void __launch_bounds__(256) projR_kernel(const float* __restrict__ Wo,
                                                    float* __restrict__ Y, int j)
{
    __shared__ __align__(16) uint32_t su[9216];
    float* Sf = (float*)(su + BH_OFF);

    const int e   = blockIdx.x;
    const int b0  = blockIdx.y * 64;
    const int z   = blockIdx.z;
    const int tid = threadIdx.x;
    const int warp = tid >> 5, lane = tid & 31;

    const float* Ag = Wo + (size_t)(z * 64) * 513 + j * 64;
    const float* Bg = g_Hep + (size_t)(hb(j) + e) * 16384 + (size_t)b0 * 64;

    float acc[4][4];
#pragma unroll
    for (int q = 0; q < 4; q++)
#pragma unroll
        for (int u = 0; u < 4; u++) acc[q][u] = 0.f;

    stage_AB(su, Ag, 513, 0, Bg, 64, tid);
    __syncthreads();
    mma_block(su, warp, lane, acc);
    __syncthreads();
    acc_to_S(Sf, warp, lane, acc);
    __syncthreads();

    const int o0 = z * 64;
    const float* Rpar = (j < 7)
        ? g_R + (size_t)(hb(j + 1) + (e >> 1)) * 32768
        : nullptr;
    for (int i = tid; i < 64 * 16; i += 256) {
        int col = i >> 4, rq = i & 15;
        float4 s = *(float4*)&Sf[(size_t)col * 68 + rq * 4];
        if (j < 7) {
            float4 p = *(const float4*)&Rpar[(size_t)(b0 + col) * 128 + o0 + rq * 4];
            s.x += p.x; s.y += p.y; s.z += p.z; s.w += p.w;
        } else {
            s.x += Wo[(size_t)(o0 + rq * 4 + 0) * 513 + 512];
            s.y += Wo[(size_t)(o0 + rq * 4 + 1) * 513 + 512];
            s.z += Wo[(size_t)(o0 + rq * 4 + 2) * 513 + 512];
            s.w += Wo[(size_t)(o0 + rq * 4 + 3) * 513 + 512];
        }
        if (j == 0) {
            float4 y = make_float4(ftanh(s.x), ftanh(s.y), ftanh(s.z), ftanh(s.w));
            *(float4*)&Y[((size_t)e * 256 + b0 + col) * 128 + o0 + rq * 4] = y;
        } else {
            *(float4*)&g_R[(size_t)(hb(j) + e) * 32768 +
                           (size_t)(b0 + col) * 128 + o0 + rq * 4] = s;
        }
    }
}

// ---------------------------------------------------------------------------
// seq<C>: H[m] = tanh(G'[m] + C1[(m-1)>>1] + W_CC @ H[m-1])
// (G' already folds all C streams with s>=2 via gsum.)
// grid 128 CTAs x 2 batch cols, 128 threads; prefetch depth 8.
// ---------------------------------------------------------------------------
template <int C>
__global__ void __launch_bounds__(128) seq_kernel(const float* __restrict__ Wh)
{
    constexpr int  U    = 512 >> C;
    constexpr bool HASC = (C < 7);
    constexpr int  HB   = 1024 - (1024 >> C);
    constexpr int  csl[8] = {0, 0, 256, 512, 704, 832, 912, 960};
    constexpr int  C1B  = HASC ? (csl[C + 1] + C * (512 >> (C + 1))) : 0;
    constexpr int  D    = (U < 8) ? U : 8;

    const int tid = threadIdx.x;
    const int lb  = tid >> 6;
    const int r   = tid & 63;
    const int b   = blockIdx.x * 2 + lb;
    const int off = b * 64 + r;

    __shared__ float Ws[64][65];
    __shared__ float Hs[2][2][64];

    for (int i = tid; i < 4096; i += 128)
        Ws[i >> 6][i & 63] = Wh[(size_t)(C * 64 + (i >> 6)) * 513 + C * 64 + (i & 63)];
    __syncthreads();

    float w[64];
#pragma unroll
    for (int q = 0; q < 64; q++) w[q] = Ws[r][q];

    const float* Gb  = g_G + (size_t)HB * 16384;
    const float* Cb  = g_C + (size_t)C1B * 16384;
    float*       Hbp = g_Hep + (size_t)HB * 16384;

    float gv[D], cv[D];
#pragma unroll
    for (int i = 0; i < D; i++) {
        gv[i] = Gb[(size_t)i * 16384 + off];
        cv[i] = 0.f;
        if (HASC && i >= 1) cv[i] = Cb[(size_t)((i - 1) >> 1) * 16384 + off];
    }

    for (int m0 = 0; m0 < U; m0 += D) {
#pragma unroll
        for (int i = 0; i < D; i++) {
            const int m  = m0 + i;
            const int rb = m & 1;
            float a = gv[i];
            if (m > 0) {
                float a0 = 0.f, a1 = 0.f, a2 = 0.f, a3 = 0.f;
#pragma unroll
                for (int q = 0; q < 64; q += 4) {
                    float4 hv = *(const float4*)&Hs[rb][lb][q];
                    a0 += w[q + 0] * hv.x;
                    a1 += w[q + 1] * hv.y;
                    a2 += w[q + 2] * hv.z;
                    a3 += w[q + 3] * hv.w;
                }
                a += (a0 + a1) + (a2 + a3);
                if (HASC) a += cv[i];
            }
            float h = ftanh(a);
            Hbp[(size_t)m * 16384 + off] = h;
            Hs[rb ^ 1][lb][r] = h;
            const int mf = m + D;
            if (mf < U) {
                gv[i] = Gb[(size_t)mf * 16384 + off];
                if (HASC) cv[i] = Cb[(size_t)((mf - 1) >> 1) * 16384 + off];
            }
            __syncthreads();
        }
    }
}

// ---------------------------------------------------------------------------
// final H: out[T*B*NO + (j*64+r)*256 + b] = H_j[last epoch][b][r] (transpose)
// ---------------------------------------------------------------------------
__global__ void __launch_bounds__(256) finalH_kernel(float* __restrict__ out)
{
    __shared__ float S[64][65];
    const int j   = blockIdx.x;
    const int b0  = blockIdx.y * 64;
    const int tid = threadIdx.x;
    const int e   = (512 >> j) - 1;
    const float* Hj = g_Hep + (size_t)(hb(j) + e) * 16384;

    for (int i = tid; i < 4096; i += 256) {
        int rr = i & 63, bb = i >> 6;
        S[bb][rr] = Hj[(size_t)(b0 + bb) * 64 + rr];
    }
    __syncthreads();
    for (int i = tid; i < 4096; i += 256) {
        int bb = i & 63, rr = i >> 6;
        out[(size_t)T_STEPS * B_SZ * NO_SZ + (size_t)(j * 64 + rr) * 256 + b0 + bb] =
            S[bb][rr];
    }
}

// ---------------------------------------------------------------------------
// Launch.
//   main: g0_hi -> seq<j> -> projC(urgent z=j-1) -> ...
//   s1  : g0_lo (levels 3..0)
//   s2  : projR chain (R_7..R_0 -> Y), join at end
//   s3  : projC deferred (z<=j-2) + gsum<C>; seq<C> gates on evGS[C]
// ---------------------------------------------------------------------------
static cudaStream_t s_s1 = nullptr, s_s2 = nullptr, s_s3 = nullptr;
static cudaEvent_t  s_ev0, s_evG0, s_evH[8], s_evR0, s_evGS[6];
static int s_state = 0;

static bool ensure_streams()
{
    if (s_state) return s_state > 0;
    bool ok = true;
    ok &= cudaStreamCreateWithFlags(&s_s1, cudaStreamNonBlocking) == cudaSuccess;
    ok &= cudaStreamCreateWithFlags(&s_s2, cudaStreamNonBlocking) == cudaSuccess;
    ok &= cudaStreamCreateWithFlags(&s_s3, cudaStreamNonBlocking) == cudaSuccess;
    ok &= cudaEventCreateWithFlags(&s_ev0,  cudaEventDisableTiming) == cudaSuccess;
    ok &= cudaEventCreateWithFlags(&s_evG0, cudaEventDisableTiming) == cudaSuccess;
    ok &= cudaEventCreateWithFlags(&s_evR0, cudaEventDisableTiming) == cudaSuccess;
    for (int i = 0; i < 8; i++)
        ok &= cudaEventCreateWithFlags(&s_evH[i], cudaEventDisableTiming) == cudaSuccess;
    for (int i = 0; i < 6; i++)
        ok &= cudaEventCreateWithFlags(&s_evGS[i], cudaEventDisableTiming) == cudaSuccess;
    s_state = ok ? 1 : -1;
    return ok;
}

extern "C" void kernel_launch(void* const* d_in, const int* in_sizes, int n_in,
                              void* d_out, int out_size)
{
    const float* X  = nullptr;
    const float* Wi = nullptr;
    const float* Wh = nullptr;
    const float* Wo = nullptr;
    for (int i = 0; i < n_in; i++) {
        switch (in_sizes[i]) {
            case 512 * 256 * 128: X  = (const float*)d_in[i]; break;
            case 512 * 129:       Wi = (const float*)d_in[i]; break;
            case 512 * 513:       Wh = (const float*)d_in[i]; break;
            case 128 * 513:       Wo = (const float*)d_in[i]; break;
            default: break;
        }
    }
    float* out = (float*)d_out;

    if (!ensure_streams()) {
        // -------- Fallback: single-stream chain ----------------------------
        g0_kernel<<<dim3(1020, 4), 256>>>(X, Wi, Wh, 0);
        seq_kernel<7><<<128, 128>>>(Wh);
        projR_kernel<<<dim3(4, 4, 2), 256>>>(Wo, out, 7);
        projC_kernel<<<dim3(4, 4, 7), 256>>>(Wh, 7, 0);
        seq_kernel<6><<<128, 128>>>(Wh);
        projR_kernel<<<dim3(8, 4, 2), 256>>>(Wo, out, 6);
        projC_kernel<<<dim3(8, 4, 6), 256>>>(Wh, 6, 0);
        gsum_kernel<<<dim3(15, 4), 256>>>(5);
        seq_kernel<5><<<128, 128>>>(Wh);
        projR_kernel<<<dim3(16, 4, 2), 256>>>(Wo, out, 5);
        projC_kernel<<<dim3(16, 4, 5), 256>>>(Wh, 5, 0);
        gsum_kernel<<<dim3(31, 4), 256>>>(4);
        seq_kernel<4><<<128, 128>>>(Wh);
        projR_kernel<<<dim3(32, 4, 2), 256>>>(Wo, out, 4);
        projC_kernel<<<dim3(32, 4, 4), 256>>>(Wh, 4, 0);
        gsum_kernel<<<dim3(63, 4), 256>>>(3);
        seq_kernel<3><<<128, 128>>>(Wh);
        projR_kernel<<<dim3(64, 4, 2), 256>>>(Wo, out, 3);
        projC_kernel<<<dim3(64, 4, 3), 256>>>(Wh, 3, 0);
        gsum_kernel<<<dim3(127, 4), 256>>>(2);
        seq_kernel<2><<<128, 128>>>(Wh);
        projR_kernel<<<dim3(128, 4, 2), 256>>>(Wo, out, 2);
        projC_kernel<<<dim3(128, 4, 2), 256>>>(Wh, 2, 0);
        gsum_kernel<<<dim3(255, 4), 256>>>(1);
        seq_kernel<1><<<128, 128>>>(Wh);
        projR_kernel<<<dim3(256, 4, 2), 256>>>(Wo, out, 1);
        projC_kernel<<<dim3(256, 4, 1), 256>>>(Wh, 1, 0);
        gsum_kernel<<<dim3(511, 4), 256>>>(0);
        seq_kernel<0><<<128, 128>>>(Wh);
        projR_kernel<<<dim3(512, 4, 2), 256>>>(Wo, out, 0);
        finalH_kernel<<<dim3(8, 4), 256>>>(out);
        return;
    }

    cudaStream_t s1 = s_s1, s2 = s_s2, s3 = s_s3;

    // Fork: g0_lo (levels 3..0, tiles 0..959) on s1.
    cudaEventRecord(s_ev0, 0);
    cudaStreamWaitEvent(s1, s_ev0, 0);
    g0_kernel<<<dim3(960, 4), 256, 0, s1>>>(X, Wi, Wh, 0);
    cudaEventRecord(s_evG0, s1);

    // Main: g0_hi (levels 7..4, tiles 960..1019).
    g0_kernel<<<dim3(60, 4), 256>>>(X, Wi, Wh, 960);

    // ---- level 7 ----
    seq_kernel<7><<<128, 128>>>(Wh);
    cudaEventRecord(s_evH[7], 0);
    cudaStreamWaitEvent(s2, s_evH[7], 0);
    projR_kernel<<<dim3(4, 4, 2), 256, 0, s2>>>(Wo, out, 7);
    cudaStreamWaitEvent(s3, s_evH[7], 0);
    projC_kernel<<<dim3(4, 4, 6), 256, 0, s3>>>(Wh, 7, 0);   // deferred z=0..5
    gsum_kernel<<<dim3(15, 4), 256, 0, s3>>>(5);
    cudaEventRecord(s_evGS[5], s3);
    projC_kernel<<<dim3(4, 4, 1), 256>>>(Wh, 7, 6);          // urgent z=6

    // ---- level 6 ----
    seq_kernel<6><<<128, 128>>>(Wh);
    cudaEventRecord(s_evH[6], 0);
    cudaStreamWaitEvent(s2, s_evH[6], 0);
    projR_kernel<<<dim3(8, 4, 2), 256, 0, s2>>>(Wo, out, 6);
    cudaStreamWaitEvent(s3, s_evH[6], 0);
    projC_kernel<<<dim3(8, 4, 5), 256, 0, s3>>>(Wh, 6, 0);   // deferred z=0..4
    gsum_kernel<<<dim3(31, 4), 256, 0, s3>>>(4);
    cudaEventRecord(s_evGS[4], s3);
    projC_kernel<<<dim3(8, 4, 1), 256>>>(Wh, 6, 5);          // urgent z=5

    // ---- level 5 ----
    cudaStreamWaitEvent(0, s_evGS[5], 0);
    seq_kernel<5><<<128, 128>>>(Wh);
    cudaEventRecord(s_evH[5], 0);
    cudaStreamWaitEvent(s2, s_evH[5], 0);
    projR_kernel<<<dim3(16, 4, 2), 256, 0, s2>>>(Wo, out, 5);
    cudaStreamWaitEvent(s3, s_evG0, 0);                      // gsum<3> reads g0_lo G
    cudaStreamWaitEvent(s3, s_evH[5], 0);
    projC_kernel<<<dim3(16, 4, 4), 256, 0, s3>>>(Wh, 5, 0);  // deferred z=0..3
    gsum_kernel<<<dim3(63, 4), 256, 0, s3>>>(3);
    cudaEventRecord(s_evGS[3], s3);
    projC_kernel<<<dim3(16, 4, 1), 256>>>(Wh, 5, 4);         // urgent z=4

    // ---- level 4 ----
    cudaStreamWaitEvent(0, s_evGS[4], 0);
    seq_kernel<4><<<128, 128>>>(Wh);
    cudaEventRecord(s_evH[4], 0);
    cudaStreamWaitEvent(s2, s_evH[4], 0);
    projR_kernel<<<dim3(32, 4, 2), 256, 0, s2>>>(Wo, out, 4);
    cudaStreamWaitEvent(s3, s_evH[4], 0);
    projC_kernel<<<dim3(32, 4, 3), 256, 0, s3>>>(Wh, 4, 0);  // deferred z=0..2
    gsum_kernel<<<dim3(127, 4), 256, 0, s3>>>(2);
    cudaEventRecord(s_evGS[2], s3);
    projC_kernel<<<dim3(32, 4, 1), 256>>>(Wh, 4, 3);         // urgent z=3

    // ---- level 3 ----
    cudaStreamWaitEvent(0, s_evGS[3], 0);
    seq_kernel<3><<<128, 128>>>(Wh);
    cudaEventRecord(s_evH[3], 0);
    cudaStreamWaitEvent(s2, s_evH[3], 0);
    projR_kernel<<<dim3(64, 4, 2), 256, 0, s2>>>(Wo, out, 3);
    cudaStreamWaitEvent(s3, s_evH[3], 0);
    projC_kernel<<<dim3(64, 4, 2), 256, 0, s3>>>(Wh, 3, 0);  // deferred z=0..1
    gsum_kernel<<<dim3(255, 4), 256, 0, s3>>>(1);
    cudaEventRecord(s_evGS[1], s3);
    projC_kernel<<<dim3(64, 4, 1), 256>>>(Wh, 3, 2);         // urgent z=2

    // ---- level 2 ----
    cudaStreamWaitEvent(0, s_evGS[2], 0);
    seq_kernel<2><<<128, 128>>>(Wh);
    cudaEventRecord(s_evH[2], 0);
    cudaStreamWaitEvent(s2, s_evH[2], 0);
    projR_kernel<<<dim3(128, 4, 2), 256, 0, s2>>>(Wo, out, 2);
    cudaStreamWaitEvent(s3, s_evH[2], 0);
    projC_kernel<<<dim3(128, 4, 1), 256, 0, s3>>>(Wh, 2, 0); // deferred z=0
    gsum_kernel<<<dim3(511, 4), 256, 0, s3>>>(0);
    cudaEventRecord(s_evGS[0], s3);
    projC_kernel<<<dim3(128, 4, 1), 256>>>(Wh, 2, 1);        // urgent z=1

    // ---- level 1 ----
    cudaStreamWaitEvent(0, s_evGS[1], 0);
    seq_kernel<1><<<128, 128>>>(Wh);
    cudaEventRecord(s_evH[1], 0);
    cudaStreamWaitEvent(s2, s_evH[1], 0);
    projR_kernel<<<dim3(256, 4, 2), 256, 0, s2>>>(Wo, out, 1);
    projC_kernel<<<dim3(256, 4, 1), 256>>>(Wh, 1, 0);        // urgent z=0

    // ---- level 0 ----
    cudaStreamWaitEvent(0, s_evGS[0], 0);
    seq_kernel<0><<<128, 128>>>(Wh);
    cudaEventRecord(s_evH[0], 0);
    cudaStreamWaitEvent(s2, s_evH[0], 0);
    projR_kernel<<<dim3(512, 4, 2), 256, 0, s2>>>(Wo, out, 0);  // writes Y
    cudaEventRecord(s_evR0, s2);

    finalH_kernel<<<dim3(8, 4), 256>>>(out);
    cudaStreamWaitEvent(0, s_evR0, 0);
}